// round 2
// baseline (speedup 1.0000x reference)
#include <cuda_runtime.h>

typedef unsigned long long u64;
#define DEV __device__ __forceinline__

static constexpr int Bb   = 2;
static constexpr int Ls   = 2048;
static constexpr int DM   = 768;
static constexpr int Hh   = 12;
static constexpr int FEAT = 16;
static constexpr int HD   = 64;
static constexpr int NR   = Bb * Ls;   // 4096 total rows

// scratch (device globals; no allocation allowed)
__device__ float g_q[NR * Hh * FEAT];  // [n][h*16+f]
__device__ float g_k[NR * Hh * FEAT];
__device__ float g_v[NR * DM];         // [n][h*64+e]
__device__ float g_y[NR * DM];         // attention output, [n][h*64+e]

// ---------------- f32x2 helpers (packed fp32 pairs, 2x FFMA throughput) ---
DEV u64 pack2(float lo, float hi) {
    u64 r; asm("mov.b64 %0, {%1, %2};" : "=l"(r) : "f"(lo), "f"(hi)); return r;
}
DEV void unpack2(u64 v, float &lo, float &hi) {
    asm("mov.b64 {%0, %1}, %2;" : "=f"(lo), "=f"(hi) : "l"(v));
}
DEV u64 fma2(u64 a, u64 b, u64 c) {
    u64 d; asm("fma.rn.f32x2 %0, %1, %2, %3;" : "=l"(d) : "l"(a), "l"(b), "l"(c));
    return d;
}

// ---------------- NT GEMM: Y[n,o] = sum_d X[n,d] * W[o,d] ------------------
// Tile 64(n) x 64(o), 128 threads, 4x8 micro-tile (f32x2 along o), K-panel 32.
// blockIdx.z selects (W0,Y0) / (W1,Y1) so Wq/Wk share one launch.
__global__ __launch_bounds__(128) void gemm_nt(const float* __restrict__ X,
                                               const float* __restrict__ W0,
                                               const float* __restrict__ W1,
                                               float* __restrict__ Y0,
                                               float* __restrict__ Y1,
                                               int Dout)
{
    __shared__ float XsT[32][68];   // [d][n], padded (272B rows, 16B aligned)
    __shared__ float WsT[32][68];   // [d][o]

    const float* __restrict__ W = blockIdx.z ? W1 : W0;
    float* __restrict__ Y       = blockIdx.z ? Y1 : Y0;

    const int t  = threadIdx.x;
    const int nb = blockIdx.x, ob = blockIdx.y;
    const int tr = t >> 3;           // 0..15  -> rows n0 = 4*tr
    const int te = t & 7;            // 0..7   -> o groups {4*te, 32+4*te}

    u64 acc[4][2][2];
    #pragma unroll
    for (int i = 0; i < 4; i++)
        #pragma unroll
        for (int jj = 0; jj < 2; jj++)
            #pragma unroll
            for (int j = 0; j < 2; j++) acc[i][jj][j] = 0ull;

    const float* Xb = X + (size_t)nb * 64 * DM;
    const float* Wb = W + (size_t)ob * 64 * DM;

    for (int d0 = 0; d0 < DM; d0 += 32) {
        __syncthreads();
        // fill XsT, WsT: 64 rows x 32 d each -> 512 float4 each, 4/thread each
        #pragma unroll
        for (int r = 0; r < 4; r++) {
            int i = t + 128 * r;
            int n = i >> 3, dj = i & 7;
            float4 v = *(const float4*)(Xb + (size_t)n * DM + d0 + dj * 4);
            XsT[dj*4+0][n] = v.x; XsT[dj*4+1][n] = v.y;
            XsT[dj*4+2][n] = v.z; XsT[dj*4+3][n] = v.w;
            float4 w = *(const float4*)(Wb + (size_t)n * DM + d0 + dj * 4);
            WsT[dj*4+0][n] = w.x; WsT[dj*4+1][n] = w.y;
            WsT[dj*4+2][n] = w.z; WsT[dj*4+3][n] = w.w;
        }
        __syncthreads();

        #pragma unroll
        for (int d = 0; d < 32; d++) {
            float4 a = *(const float4*)&XsT[d][4 * tr];
            u64 as[4];
            as[0] = pack2(a.x, a.x); as[1] = pack2(a.y, a.y);
            as[2] = pack2(a.z, a.z); as[3] = pack2(a.w, a.w);
            ulonglong2 b0 = *(const ulonglong2*)&WsT[d][4 * te];
            ulonglong2 b1 = *(const ulonglong2*)&WsT[d][32 + 4 * te];
            #pragma unroll
            for (int i = 0; i < 4; i++) {
                acc[i][0][0] = fma2(as[i], b0.x, acc[i][0][0]);
                acc[i][0][1] = fma2(as[i], b0.y, acc[i][0][1]);
                acc[i][1][0] = fma2(as[i], b1.x, acc[i][1][0]);
                acc[i][1][1] = fma2(as[i], b1.y, acc[i][1][1]);
            }
        }
    }

    #pragma unroll
    for (int i = 0; i < 4; i++) {
        int n = nb * 64 + 4 * tr + i;
        float* Yr = Y + (size_t)n * Dout + ob * 64;
        #pragma unroll
        for (int jj = 0; jj < 2; jj++) {
            float lo0, hi0, lo1, hi1;
            unpack2(acc[i][jj][0], lo0, hi0);
            unpack2(acc[i][jj][1], lo1, hi1);
            float4 o = make_float4(lo0, hi0, lo1, hi1);
            *(float4*)(Yr + jj * 32 + te * 4) = o;
        }
    }
}

// ---------------- fused Based attention --------------------------------
// Per (b,h): w[n,m] = (1 + s/4 + s^2/32) * (m<=n ? 2 : 1), s = q_n . k_m (16d)
// y[n] = (sum_m w * v_m) / (sum_m w)
// Grid: (L/64 row tiles, B*H). 128 threads (two 64-thread halves split m in A).
__global__ __launch_bounds__(128) void attn_kernel()
{
    __shared__ float Ks[32][16];
    __shared__ float Vs[32][68];
    __shared__ float Ws[32][68];    // w tile, [m][n-local], padded
    __shared__ float denom_s[2][64];

    const int t  = threadIdx.x;
    const int rb = blockIdx.x;
    const int bh = blockIdx.y;
    const int b = bh / Hh, h = bh % Hh;

    const int rid  = t & 63;
    const int half = t >> 6;
    const int row  = rb * 64 + rid;   // this thread's phase-A row

    // q row -> packed registers
    const float* qp = g_q + ((size_t)(b * Ls + row)) * (Hh * FEAT) + h * FEAT;
    u64 q2[8];
    #pragma unroll
    for (int j = 0; j < 4; j++) {
        float4 v = *(const float4*)(qp + 4 * j);
        q2[2*j]   = pack2(v.x, v.y);
        q2[2*j+1] = pack2(v.z, v.w);
    }
    denom_s[half][rid] = 0.0f;

    const int tr = t >> 3, te = t & 7;   // phase-B mapping: rows 4*tr.., e-groups te
    u64 acc[4][2][2];
    #pragma unroll
    for (int i = 0; i < 4; i++)
        #pragma unroll
        for (int jj = 0; jj < 2; jj++)
            #pragma unroll
            for (int j = 0; j < 2; j++) acc[i][jj][j] = 0ull;

    const float* kbase = g_k + ((size_t)(b * Ls)) * (Hh * FEAT) + h * FEAT;
    const float* vbase = g_v + ((size_t)(b * Ls)) * DM + h * HD;

    for (int mt = 0; mt < Ls / 32; mt++) {
        __syncthreads();
        // fill K tile: 32x16 = 128 float4, one per thread
        {
            int m = t >> 2, dj = t & 3;
            float4 v = *(const float4*)(kbase + (size_t)(mt * 32 + m) * (Hh * FEAT) + dj * 4);
            *(float4*)&Ks[m][dj * 4] = v;
        }
        // fill V tile: 32x64 = 512 float4, four per thread
        #pragma unroll
        for (int r = 0; r < 4; r++) {
            int i = t + 128 * r;
            int m = i >> 4, dj = i & 15;
            float4 v = *(const float4*)(vbase + (size_t)(mt * 32 + m) * DM + dj * 4);
            *(float4*)&Vs[m][dj * 4] = v;
        }
        __syncthreads();

        // ---- phase A: this thread's row, 16 of 32 m (split by half) ----
        float dsum = 0.0f;
        #pragma unroll
        for (int mm = 0; mm < 16; mm++) {
            int m = half * 16 + mm;
            const u64* kr = (const u64*)&Ks[m][0];
            u64 s2 = 0ull;
            #pragma unroll
            for (int j = 0; j < 8; j++) s2 = fma2(q2[j], kr[j], s2);
            float lo, hi; unpack2(s2, lo, hi);
            float s = lo + hi;
            float a = fmaf(s, fmaf(s, 0.03125f, 0.25f), 1.0f);
            int mg = mt * 32 + m;
            float w = (mg <= row) ? (a + a) : a;
            Ws[m][rid] = w;
            dsum += w;
        }
        denom_s[half][rid] += dsum;
        __syncthreads();

        // ---- phase B: acc += w * V  (64n x 64e x 32m GEMM) ----
        #pragma unroll
        for (int m = 0; m < 32; m++) {
            float4 w4 = *(const float4*)&Ws[m][4 * tr];
            u64 ws[4];
            ws[0] = pack2(w4.x, w4.x); ws[1] = pack2(w4.y, w4.y);
            ws[2] = pack2(w4.z, w4.z); ws[3] = pack2(w4.w, w4.w);
            ulonglong2 b0 = *(const ulonglong2*)&Vs[m][4 * te];
            ulonglong2 b1 = *(const ulonglong2*)&Vs[m][32 + 4 * te];
            #pragma unroll
            for (int i = 0; i < 4; i++) {
                acc[i][0][0] = fma2(ws[i], b0.x, acc[i][0][0]);
                acc[i][0][1] = fma2(ws[i], b0.y, acc[i][0][1]);
                acc[i][1][0] = fma2(ws[i], b1.x, acc[i][1][0]);
                acc[i][1][1] = fma2(ws[i], b1.y, acc[i][1][1]);
            }
        }
    }
    __syncthreads();

    // epilogue: y = acc / denom, write to g_y[n][h*64+e]
    float* ybase = g_y + ((size_t)(b * Ls + rb * 64)) * DM + h * HD;
    #pragma unroll
    for (int i = 0; i < 4; i++) {
        int n = 4 * tr + i;
        float rz = 1.0f / (denom_s[0][n] + denom_s[1][n]);
        float* yr = ybase + (size_t)n * DM;
        #pragma unroll
        for (int jj = 0; jj < 2; jj++) {
            float lo0, hi0, lo1, hi1;
            unpack2(acc[i][jj][0], lo0, hi0);
            unpack2(acc[i][jj][1], lo1, hi1);
            float4 o = make_float4(lo0 * rz, hi0 * rz, lo1 * rz, hi1 * rz);
            *(float4*)(yr + jj * 32 + te * 4) = o;
        }
    }
}

// ---------------- launcher ------------------------------------------------
extern "C" void kernel_launch(void* const* d_in, const int* in_sizes, int n_in,
                              void* d_out, int out_size)
{
    const float* hs = (const float*)d_in[0];
    const float* Wq = (const float*)d_in[1];
    const float* Wk = (const float*)d_in[2];
    const float* Wv = (const float*)d_in[3];
    const float* Wo = (const float*)d_in[4];
    float* out = (float*)d_out;

    float *pq, *pk, *pv, *py;
    cudaGetSymbolAddress((void**)&pq, g_q);
    cudaGetSymbolAddress((void**)&pk, g_k);
    cudaGetSymbolAddress((void**)&pv, g_v);
    cudaGetSymbolAddress((void**)&py, g_y);

    dim3 blk(128);
    // q,k projections fused: [4096,768] x [192,768]^T, z picks q vs k
    gemm_nt<<<dim3(NR / 64, (Hh * FEAT) / 64, 2), blk>>>(hs, Wq, Wk, pq, pk, Hh * FEAT);
    // v projection: [4096,768] x [768,768]^T
    gemm_nt<<<dim3(NR / 64, DM / 64, 1), blk>>>(hs, Wv, Wv, pv, pv, DM);
    // fused attention
    attn_kernel<<<dim3(Ls / 64, Bb * Hh), blk>>>();
    // output projection: [4096,768] x [768,768]^T
    gemm_nt<<<dim3(NR / 64, DM / 64, 1), blk>>>(py, Wo, Wo, out, out, DM);
}

// round 5
// speedup vs baseline: 1.4038x; 1.4038x over previous
#include <cuda_runtime.h>
#include <cuda_bf16.h>

typedef unsigned long long u64;
typedef unsigned int u32;
#define DEV __device__ __forceinline__

static constexpr int Bb   = 2;
static constexpr int Ls   = 2048;
static constexpr int DM   = 768;
static constexpr int Hh   = 12;
static constexpr int FEAT = 16;
static constexpr int HD   = 64;
static constexpr int NR   = Bb * Ls;   // 4096 rows
static constexpr int K3   = 3 * DM;    // 2304: [hi|lo|hi] x [hi|hi|lo]
static constexpr int NP   = K3 / 32;   // 72 k-panels

// ---------------- scratch (device globals; no allocation allowed) ---------
__device__ float g_q[NR * Hh * FEAT];
__device__ float g_k[NR * Hh * FEAT];
__device__ float g_v[NR * DM];
__device__ float g_y[NR * DM];
__device__ __nv_bfloat16 g_xs [NR * K3];
__device__ __nv_bfloat16 g_ys [NR * K3];
__device__ __nv_bfloat16 g_wqs[(Hh*FEAT) * K3];
__device__ __nv_bfloat16 g_wks[(Hh*FEAT) * K3];
__device__ __nv_bfloat16 g_wvs[DM * K3];
__device__ __nv_bfloat16 g_wos[DM * K3];

// ---------------- f32x2 helpers -------------------------------------------
DEV u64 pack2(float lo, float hi) {
    u64 r; asm("mov.b64 %0, {%1, %2};" : "=l"(r) : "f"(lo), "f"(hi)); return r;
}
DEV void unpack2(u64 v, float &lo, float &hi) {
    asm("mov.b64 {%0, %1}, %2;" : "=f"(lo), "=f"(hi) : "l"(v));
}
DEV u64 fma2(u64 a, u64 b, u64 c) {
    u64 d; asm("fma.rn.f32x2 %0, %1, %2, %3;" : "=l"(d) : "l"(a), "l"(b), "l"(c));
    return d;
}

// ---------------- smem / async helpers ------------------------------------
DEV u32 smem_u32(const void* p) {
    u32 a; asm("{ .reg .u64 t; cvta.to.shared.u64 t, %1; cvt.u32.u64 %0, t; }"
               : "=r"(a) : "l"(p));
    return a;
}
DEV void cp_async16(u32 saddr, const void* gaddr) {
    asm volatile("cp.async.cg.shared.global [%0], [%1], 16;"
                 :: "r"(saddr), "l"(gaddr) : "memory");
}
DEV void cp_commit() { asm volatile("cp.async.commit_group;" ::: "memory"); }
template<int N> DEV void cp_wait() {
    asm volatile("cp.async.wait_group %0;" :: "n"(N) : "memory");
}
DEV void ldm_x4(u32 &r0, u32 &r1, u32 &r2, u32 &r3, u32 addr) {
    asm volatile("ldmatrix.sync.aligned.m8n8.x4.shared.b16 {%0,%1,%2,%3}, [%4];"
                 : "=r"(r0), "=r"(r1), "=r"(r2), "=r"(r3) : "r"(addr));
}
DEV void mma_bf16(float &c0, float &c1, float &c2, float &c3,
                  u32 a0, u32 a1, u32 a2, u32 a3, u32 b0, u32 b1) {
    asm volatile(
        "mma.sync.aligned.m16n8k16.row.col.f32.bf16.bf16.f32 "
        "{%0,%1,%2,%3}, {%4,%5,%6,%7}, {%8,%9}, {%0,%1,%2,%3};"
        : "+f"(c0), "+f"(c1), "+f"(c2), "+f"(c3)
        : "r"(a0), "r"(a1), "r"(a2), "r"(a3), "r"(b0), "r"(b1));
}

// ---------------- fp32 -> bf16 3-way split --------------------------------
// src [R,768] fp32 -> dst [R,2304] bf16.
// modeA=1 (left operand):  [hi | lo | hi]
// modeA=0 (right operand): [hi | hi | lo]
__global__ void split_bf16(const float* __restrict__ src,
                           __nv_bfloat16* __restrict__ dst, int total4, int modeA)
{
    int idx = blockIdx.x * blockDim.x + threadIdx.x;
    if (idx >= total4) return;
    int r  = idx / 192;
    int c4 = idx % 192;
    float4 v = *(const float4*)(src + (size_t)r * 768 + c4 * 4);
    float vv[4] = {v.x, v.y, v.z, v.w};
    __nv_bfloat16 h[4], l[4];
    #pragma unroll
    for (int i = 0; i < 4; i++) {
        h[i] = __float2bfloat16(vv[i]);
        l[i] = __float2bfloat16(vv[i] - __bfloat162float(h[i]));
    }
    __nv_bfloat162 hp0 = {h[0], h[1]}, hp1 = {h[2], h[3]};
    __nv_bfloat162 lp0 = {l[0], l[1]}, lp1 = {l[2], l[3]};
    __nv_bfloat162* d0 = (__nv_bfloat162*)(dst + (size_t)r * K3 + c4 * 4);
    __nv_bfloat162* d1 = (__nv_bfloat162*)(dst + (size_t)r * K3 + 768 + c4 * 4);
    __nv_bfloat162* d2 = (__nv_bfloat162*)(dst + (size_t)r * K3 + 1536 + c4 * 4);
    d0[0] = hp0; d0[1] = hp1;
    if (modeA) { d1[0] = lp0; d1[1] = lp1; d2[0] = hp0; d2[1] = hp1; }
    else       { d1[0] = hp0; d1[1] = hp1; d2[0] = lp0; d2[1] = lp1; }
}

// ---------------- HMMA NT GEMM: Y[n,o] = sum_k A[n,k]*B[o,k] --------------
// A [Nrows,2304] bf16, B [Dout,2304] bf16, Y [Nrows,Dout] fp32.
// Block 128n x 64o, 4 warps (warp = 32n x 64o), k-panel 32, double-buffered.
__global__ __launch_bounds__(128) void hmma_gemm(const __nv_bfloat16* __restrict__ A,
                                                 const __nv_bfloat16* __restrict__ B0,
                                                 const __nv_bfloat16* __restrict__ B1,
                                                 float* __restrict__ Y0,
                                                 float* __restrict__ Y1,
                                                 int Dout)
{
    __shared__ __align__(16) __nv_bfloat16 As[2][128][40];
    __shared__ __align__(16) __nv_bfloat16 Bs[2][64][40];

    const __nv_bfloat16* __restrict__ Bw = blockIdx.z ? B1 : B0;
    float* __restrict__ Y                = blockIdx.z ? Y1 : Y0;

    const int t = threadIdx.x, warp = t >> 5, lane = t & 31;
    const int nb = blockIdx.x, ob = blockIdx.y;

    const __nv_bfloat16* Ab = A  + (size_t)nb * 128 * K3;
    const __nv_bfloat16* Bb = Bw + (size_t)ob * 64 * K3;

    float acc[2][8][4];
    #pragma unroll
    for (int mi = 0; mi < 2; mi++)
        #pragma unroll
        for (int nf = 0; nf < 8; nf++)
            #pragma unroll
            for (int j = 0; j < 4; j++) acc[mi][nf][j] = 0.0f;

    const int ar = t >> 2, ac = t & 3;
    const int a_row = warp * 32 + (lane & 7) + ((lane >> 3) & 1) * 8;
    const int a_col = ((lane >> 4) & 1) * 8;
    const int b_row = ((lane >> 4) & 1) * 8 + (lane & 7);
    const int b_col = ((lane >> 3) & 1) * 8;

    u32 sAbase = smem_u32(&As[0][0][0]);
    u32 sBbase = smem_u32(&Bs[0][0][0]);
    const u32 ABUF = 128 * 40 * 2, BBUF = 64 * 40 * 2;

    auto load_panel = [&](int p, int buf) {
        int kp = p * 32;
        u32 sa = sAbase + buf * ABUF;
        u32 sb = sBbase + buf * BBUF;
        #pragma unroll
        for (int it = 0; it < 4; it++) {
            int r = ar + 32 * it;
            cp_async16(sa + (u32)(r * 80 + ac * 16),
                       Ab + (size_t)r * K3 + kp + ac * 8);
        }
        #pragma unroll
        for (int it = 0; it < 2; it++) {
            int r = ar + 32 * it;
            cp_async16(sb + (u32)(r * 80 + ac * 16),
                       Bb + (size_t)r * K3 + kp + ac * 8);
        }
        cp_commit();
    };

    load_panel(0, 0);

    for (int p = 0; p < NP; p++) {
        if (p + 1 < NP) { load_panel(p + 1, (p + 1) & 1); cp_wait<1>(); }
        else           { cp_wait<0>(); }
        __syncthreads();

        int buf = p & 1;
        u32 sa = sAbase + buf * ABUF;
        u32 sb = sBbase + buf * BBUF;

        #pragma unroll
        for (int k16 = 0; k16 < 32; k16 += 16) {
            u32 a[2][4];
            #pragma unroll
            for (int mi = 0; mi < 2; mi++)
                ldm_x4(a[mi][0], a[mi][1], a[mi][2], a[mi][3],
                       sa + (u32)((a_row + mi * 16) * 80 + (k16 + a_col) * 2));
            u32 b[4][4];
            #pragma unroll
            for (int g = 0; g < 4; g++)
                ldm_x4(b[g][0], b[g][1], b[g][2], b[g][3],
                       sb + (u32)((g * 16 + b_row) * 80 + (k16 + b_col) * 2));
            #pragma unroll
            for (int mi = 0; mi < 2; mi++)
                #pragma unroll
                for (int nf = 0; nf < 8; nf++) {
                    u32 bb0 = b[nf >> 1][(nf & 1) * 2];
                    u32 bb1 = b[nf >> 1][(nf & 1) * 2 + 1];
                    mma_bf16(acc[mi][nf][0], acc[mi][nf][1],
                             acc[mi][nf][2], acc[mi][nf][3],
                             a[mi][0], a[mi][1], a[mi][2], a[mi][3], bb0, bb1);
                }
        }
        __syncthreads();
    }

    const int gid = lane >> 2, tig = lane & 3;
    #pragma unroll
    for (int mi = 0; mi < 2; mi++) {
        int n0 = nb * 128 + warp * 32 + mi * 16 + gid;
        #pragma unroll
        for (int nf = 0; nf < 8; nf++) {
            int o = ob * 64 + nf * 8 + tig * 2;
            *(float2*)(Y + (size_t)n0 * Dout + o) =
                make_float2(acc[mi][nf][0], acc[mi][nf][1]);
            *(float2*)(Y + (size_t)(n0 + 8) * Dout + o) =
                make_float2(acc[mi][nf][2], acc[mi][nf][3]);
        }
    }
}

// ---------------- fused Based attention (R1 version, proven) --------------
__global__ __launch_bounds__(128) void attn_kernel()
{
    __shared__ float Ks[32][16];
    __shared__ float Vs[32][64];
    __shared__ float Ws[32][128];
    __shared__ float denom_s[128];

    const int t  = threadIdx.x;
    const int rb = blockIdx.x;
    const int bh = blockIdx.y;
    const int b = bh / Hh, h = bh % Hh;

    const int row = rb * 128 + t;

    const float* qp = g_q + ((size_t)(b * Ls + row)) * (Hh * FEAT) + h * FEAT;
    u64 q2[8];
    #pragma unroll
    for (int j = 0; j < 4; j++) {
        float4 v = *(const float4*)(qp + 4 * j);
        q2[2*j]   = pack2(v.x, v.y);
        q2[2*j+1] = pack2(v.z, v.w);
    }
    denom_s[t] = 0.0f;

    const int tr = t >> 3, te = t & 7;
    u64 acc[8][2][2];
    #pragma unroll
    for (int i = 0; i < 8; i++)
        #pragma unroll
        for (int jj = 0; jj < 2; jj++)
            #pragma unroll
            for (int j = 0; j < 2; j++) acc[i][jj][j] = 0ull;

    const float* kbase = g_k + ((size_t)(b * Ls)) * (Hh * FEAT) + h * FEAT;
    const float* vbase = g_v + ((size_t)(b * Ls)) * DM + h * HD;

    for (int mt = 0; mt < Ls / 32; mt++) {
        __syncthreads();
        {
            int m = t >> 2, dj = t & 3;
            float4 v = *(const float4*)(kbase + (size_t)(mt * 32 + m) * (Hh * FEAT) + dj * 4);
            *(float4*)&Ks[m][dj * 4] = v;
        }
        #pragma unroll
        for (int r = 0; r < 4; r++) {
            int i = t + 128 * r;
            int m = i >> 4, dj = i & 15;
            float4 v = *(const float4*)(vbase + (size_t)(mt * 32 + m) * DM + dj * 4);
            *(float4*)&Vs[m][dj * 4] = v;
        }
        __syncthreads();

        float dsum = 0.0f;
        #pragma unroll 8
        for (int m = 0; m < 32; m++) {
            const u64* kr = (const u64*)&Ks[m][0];
            u64 s2 = 0ull;
            #pragma unroll
            for (int j = 0; j < 8; j++) s2 = fma2(q2[j], kr[j], s2);
            float lo, hi; unpack2(s2, lo, hi);
            float s = lo + hi;
            float a = fmaf(s, fmaf(s, 0.03125f, 0.25f), 1.0f);
            int mg = mt * 32 + m;
            float w = (mg <= row) ? (a + a) : a;
            Ws[m][t] = w;
            dsum += w;
        }
        denom_s[t] += dsum;
        __syncthreads();

        #pragma unroll 8
        for (int m = 0; m < 32; m++) {
            float4 w0 = *(const float4*)&Ws[m][8 * tr];
            float4 w1 = *(const float4*)&Ws[m][8 * tr + 4];
            u64 ws[8];
            ws[0] = pack2(w0.x, w0.x); ws[1] = pack2(w0.y, w0.y);
            ws[2] = pack2(w0.z, w0.z); ws[3] = pack2(w0.w, w0.w);
            ws[4] = pack2(w1.x, w1.x); ws[5] = pack2(w1.y, w1.y);
            ws[6] = pack2(w1.z, w1.z); ws[7] = pack2(w1.w, w1.w);
            u64 b00 = *(const u64*)&Vs[m][4 * te];
            u64 b01 = *(const u64*)&Vs[m][4 * te + 2];
            u64 b10 = *(const u64*)&Vs[m][32 + 4 * te];
            u64 b11 = *(const u64*)&Vs[m][32 + 4 * te + 2];
            #pragma unroll
            for (int i = 0; i < 8; i++) {
                acc[i][0][0] = fma2(ws[i], b00, acc[i][0][0]);
                acc[i][0][1] = fma2(ws[i], b01, acc[i][0][1]);
                acc[i][1][0] = fma2(ws[i], b10, acc[i][1][0]);
                acc[i][1][1] = fma2(ws[i], b11, acc[i][1][1]);
            }
        }
    }
    __syncthreads();

    float* ybase = g_y + ((size_t)(b * Ls + rb * 128)) * DM + h * HD;
    #pragma unroll
    for (int i = 0; i < 8; i++) {
        int n = 8 * tr + i;
        float rz = 1.0f / denom_s[n];
        float* yr = ybase + (size_t)n * DM;
        #pragma unroll
        for (int jj = 0; jj < 2; jj++)
            #pragma unroll
            for (int j = 0; j < 2; j++) {
                float lo, hi; unpack2(acc[i][jj][j], lo, hi);
                int e = jj * 32 + te * 4 + j * 2;
                yr[e]     = lo * rz;
                yr[e + 1] = hi * rz;
            }
    }
}

// ---------------- launcher ------------------------------------------------
extern "C" void kernel_launch(void* const* d_in, const int* in_sizes, int n_in,
                              void* d_out, int out_size)
{
    const float* hs = (const float*)d_in[0];
    const float* Wq = (const float*)d_in[1];
    const float* Wk = (const float*)d_in[2];
    const float* Wv = (const float*)d_in[3];
    const float* Wo = (const float*)d_in[4];
    float* out = (float*)d_out;

    float *pq, *pk, *pv, *py;
    __nv_bfloat16 *pxs, *pys, *pwq, *pwk, *pwv, *pwo;
    cudaGetSymbolAddress((void**)&pq,  g_q);
    cudaGetSymbolAddress((void**)&pk,  g_k);
    cudaGetSymbolAddress((void**)&pv,  g_v);
    cudaGetSymbolAddress((void**)&py,  g_y);
    cudaGetSymbolAddress((void**)&pxs, g_xs);
    cudaGetSymbolAddress((void**)&pys, g_ys);
    cudaGetSymbolAddress((void**)&pwq, g_wqs);
    cudaGetSymbolAddress((void**)&pwk, g_wks);
    cudaGetSymbolAddress((void**)&pwv, g_wvs);
    cudaGetSymbolAddress((void**)&pwo, g_wos);

    // splits: left operands mode 1 ([hi|lo|hi]), right operands mode 0 ([hi|hi|lo])
    split_bf16<<<(NR*192 + 255)/256, 256>>>(hs, pxs, NR*192, 1);
    split_bf16<<<(192*192 + 255)/256, 256>>>(Wq, pwq, 192*192, 0);
    split_bf16<<<(192*192 + 255)/256, 256>>>(Wk, pwk, 192*192, 0);
    split_bf16<<<(DM*192 + 255)/256, 256>>>(Wv, pwv, DM*192, 0);
    split_bf16<<<(DM*192 + 255)/256, 256>>>(Wo, pwo, DM*192, 0);

    // projections on HMMA tensor cores
    hmma_gemm<<<dim3(NR/128, (Hh*FEAT)/64, 2), 128>>>(pxs, pwq, pwk, pq, pk, Hh*FEAT);
    hmma_gemm<<<dim3(NR/128, DM/64, 1), 128>>>(pxs, pwv, pwv, pv, pv, DM);

    // fused attention (fp32 CUDA cores)
    attn_kernel<<<dim3(Ls/128, Bb*Hh), 128>>>();

    // output projection
    split_bf16<<<(NR*192 + 255)/256, 256>>>(py, pys, NR*192, 1);
    hmma_gemm<<<dim3(NR/128, DM/64, 1), 128>>>(pys, pwo, pwo, out, out, DM);
}

// round 8
// speedup vs baseline: 2.0811x; 1.4825x over previous
#include <cuda_runtime.h>
#include <cuda_bf16.h>

typedef unsigned long long u64;
typedef unsigned int u32;
#define DEV __device__ __forceinline__

static constexpr int Bb   = 2;
static constexpr int Ls   = 2048;
static constexpr int DM   = 768;
static constexpr int Hh   = 12;
static constexpr int FEAT = 16;
static constexpr int HD   = 64;
static constexpr int NR   = Bb * Ls;   // 4096 rows
static constexpr int K3   = 3 * DM;    // 2304
static constexpr int NP   = K3 / 32;   // 72 k-panels
static constexpr int NMT  = Ls / 32;   // 64 attn m-tiles

// ---------------- scratch (device globals) --------------------------------
__device__ float g_q[NR * Hh * FEAT];
__device__ float g_k[NR * Hh * FEAT];
__device__ float g_v[NR * DM];
__device__ float g_y[NR * DM];
__device__ __nv_bfloat16 g_xs [NR * K3];
__device__ __nv_bfloat16 g_ys [NR * K3];
__device__ __nv_bfloat16 g_wqs[(Hh*FEAT) * K3];
__device__ __nv_bfloat16 g_wks[(Hh*FEAT) * K3];
__device__ __nv_bfloat16 g_wvs[DM * K3];
__device__ __nv_bfloat16 g_wos[DM * K3];
__device__ __nv_bfloat16 g_qsp[(size_t)Bb*Hh*Ls*48];   // [bh][l][hi|lo|hi]
__device__ __nv_bfloat16 g_ksp[(size_t)Bb*Hh*Ls*48];   // [bh][l][hi|hi|lo]
__device__ __nv_bfloat16 g_vsp[(size_t)Bb*Hh*128*Ls];  // [bh][r(64 hi|64 lo)][l]

// ---------------- helpers -------------------------------------------------
DEV u32 smem_u32(const void* p) {
    u32 a; asm("{ .reg .u64 t; cvta.to.shared.u64 t, %1; cvt.u32.u64 %0, t; }"
               : "=r"(a) : "l"(p));
    return a;
}
DEV void cp_async16(u32 saddr, const void* gaddr) {
    asm volatile("cp.async.cg.shared.global [%0], [%1], 16;"
                 :: "r"(saddr), "l"(gaddr) : "memory");
}
DEV void cp_commit() { asm volatile("cp.async.commit_group;" ::: "memory"); }
template<int N> DEV void cp_wait() {
    asm volatile("cp.async.wait_group %0;" :: "n"(N) : "memory");
}
DEV void ldm_x4(u32 &r0, u32 &r1, u32 &r2, u32 &r3, u32 addr) {
    asm volatile("ldmatrix.sync.aligned.m8n8.x4.shared.b16 {%0,%1,%2,%3}, [%4];"
                 : "=r"(r0), "=r"(r1), "=r"(r2), "=r"(r3) : "r"(addr));
}
DEV void mma_bf16(float &c0, float &c1, float &c2, float &c3,
                  u32 a0, u32 a1, u32 a2, u32 a3, u32 b0, u32 b1) {
    asm volatile(
        "mma.sync.aligned.m16n8k16.row.col.f32.bf16.bf16.f32 "
        "{%0,%1,%2,%3}, {%4,%5,%6,%7}, {%8,%9}, {%0,%1,%2,%3};"
        : "+f"(c0), "+f"(c1), "+f"(c2), "+f"(c3)
        : "r"(a0), "r"(a1), "r"(a2), "r"(a3), "r"(b0), "r"(b1));
}

// ---------------- fp32 -> bf16 3-way split (GEMM operands) ----------------
__global__ void split_bf16(const float* __restrict__ src,
                           __nv_bfloat16* __restrict__ dst, int total4, int modeA)
{
    int idx = blockIdx.x * blockDim.x + threadIdx.x;
    if (idx >= total4) return;
    int r  = idx / 192;
    int c4 = idx % 192;
    float4 v = *(const float4*)(src + (size_t)r * 768 + c4 * 4);
    float vv[4] = {v.x, v.y, v.z, v.w};
    __nv_bfloat16 h[4], l[4];
    #pragma unroll
    for (int i = 0; i < 4; i++) {
        h[i] = __float2bfloat16(vv[i]);
        l[i] = __float2bfloat16(vv[i] - __bfloat162float(h[i]));
    }
    __nv_bfloat162 hp0 = {h[0], h[1]}, hp1 = {h[2], h[3]};
    __nv_bfloat162 lp0 = {l[0], l[1]}, lp1 = {l[2], l[3]};
    __nv_bfloat162* d0 = (__nv_bfloat162*)(dst + (size_t)r * K3 + c4 * 4);
    __nv_bfloat162* d1 = (__nv_bfloat162*)(dst + (size_t)r * K3 + 768 + c4 * 4);
    __nv_bfloat162* d2 = (__nv_bfloat162*)(dst + (size_t)r * K3 + 1536 + c4 * 4);
    d0[0] = hp0; d0[1] = hp1;
    if (modeA) { d1[0] = lp0; d1[1] = lp1; d2[0] = hp0; d2[1] = hp1; }
    else       { d1[0] = hp0; d1[1] = hp1; d2[0] = lp0; d2[1] = lp1; }
}

// ---------------- q/k split to head-major [bh][l][48] ---------------------
__global__ void split_qk_attn(const float* __restrict__ src,
                              __nv_bfloat16* __restrict__ dst, int modeA)
{
    int idx = blockIdx.x * blockDim.x + threadIdx.x;
    if (idx >= NR * Hh) return;
    int n = idx / Hh, h = idx % Hh;
    int b = n / Ls, l = n % Ls;
    const float* sp = src + (size_t)n * (Hh*FEAT) + h * FEAT;
    __nv_bfloat16 buf[48];
    #pragma unroll
    for (int i = 0; i < 16; i++) {
        float v = sp[i];
        __nv_bfloat16 hi = __float2bfloat16(v);
        __nv_bfloat16 lo = __float2bfloat16(v - __bfloat162float(hi));
        buf[i] = hi;
        if (modeA) { buf[16+i] = lo; buf[32+i] = hi; }
        else       { buf[16+i] = hi; buf[32+i] = lo; }
    }
    uint4* d = (uint4*)(dst + ((size_t)(b*Hh+h)*Ls + l) * 48);
    const uint4* s4 = (const uint4*)buf;
    #pragma unroll
    for (int i = 0; i < 6; i++) d[i] = s4[i];
}

// ---------------- v split TRANSPOSED: [bh][r=e(hi0-63|lo64-127)][l] -------
__global__ void split_v_attn(const float* __restrict__ src,
                             __nv_bfloat16* __restrict__ dst)
{
    // one thread per (bh, l8, r): 8 l-values. lanes vary r -> coalesced reads.
    int idx = blockIdx.x * blockDim.x + threadIdx.x;
    if (idx >= Bb * Hh * (Ls/8) * 128) return;
    int r   = idx & 127;
    int l8  = (idx >> 7) & (Ls/8 - 1);
    int bh  = idx >> (7 + 8);          // Ls/8 = 256 = 2^8
    int b = bh / Hh, h = bh % Hh;
    int e = r & 63;
    bool low = r >= 64;

    __nv_bfloat16 outb[8];
    #pragma unroll
    for (int i = 0; i < 8; i++) {
        float v = src[((size_t)(b * Ls + l8 * 8 + i)) * DM + h * HD + e];
        __nv_bfloat16 hi = __float2bfloat16(v);
        outb[i] = low ? __float2bfloat16(v - __bfloat162float(hi)) : hi;
    }
    *(uint4*)(dst + ((size_t)bh * 128 + r) * Ls + l8 * 8) = *(const uint4*)outb;
}

// ---------------- HMMA NT GEMM (proven R5) --------------------------------
__global__ __launch_bounds__(128) void hmma_gemm(const __nv_bfloat16* __restrict__ A,
                                                 const __nv_bfloat16* __restrict__ B0,
                                                 const __nv_bfloat16* __restrict__ B1,
                                                 float* __restrict__ Y0,
                                                 float* __restrict__ Y1,
                                                 int Dout)
{
    __shared__ __align__(16) __nv_bfloat16 As[2][128][40];
    __shared__ __align__(16) __nv_bfloat16 Bs[2][64][40];

    const __nv_bfloat16* __restrict__ Bw = blockIdx.z ? B1 : B0;
    float* __restrict__ Y                = blockIdx.z ? Y1 : Y0;

    const int t = threadIdx.x, warp = t >> 5, lane = t & 31;
    const int nb = blockIdx.x, ob = blockIdx.y;

    const __nv_bfloat16* Ab = A  + (size_t)nb * 128 * K3;
    const __nv_bfloat16* Bb = Bw + (size_t)ob * 64 * K3;

    float acc[2][8][4];
    #pragma unroll
    for (int mi = 0; mi < 2; mi++)
        #pragma unroll
        for (int nf = 0; nf < 8; nf++)
            #pragma unroll
            for (int j = 0; j < 4; j++) acc[mi][nf][j] = 0.0f;

    const int ar = t >> 2, ac = t & 3;
    const int a_row = warp * 32 + (lane & 7) + ((lane >> 3) & 1) * 8;
    const int a_col = ((lane >> 4) & 1) * 8;
    const int b_row = ((lane >> 4) & 1) * 8 + (lane & 7);
    const int b_col = ((lane >> 3) & 1) * 8;

    u32 sAbase = smem_u32(&As[0][0][0]);
    u32 sBbase = smem_u32(&Bs[0][0][0]);
    const u32 ABUF = 128 * 40 * 2, BBUF = 64 * 40 * 2;

    auto load_panel = [&](int p, int buf) {
        int kp = p * 32;
        u32 sa = sAbase + buf * ABUF;
        u32 sb = sBbase + buf * BBUF;
        #pragma unroll
        for (int it = 0; it < 4; it++) {
            int r = ar + 32 * it;
            cp_async16(sa + (u32)(r * 80 + ac * 16),
                       Ab + (size_t)r * K3 + kp + ac * 8);
        }
        #pragma unroll
        for (int it = 0; it < 2; it++) {
            int r = ar + 32 * it;
            cp_async16(sb + (u32)(r * 80 + ac * 16),
                       Bb + (size_t)r * K3 + kp + ac * 8);
        }
        cp_commit();
    };

    load_panel(0, 0);

    for (int p = 0; p < NP; p++) {
        if (p + 1 < NP) { load_panel(p + 1, (p + 1) & 1); cp_wait<1>(); }
        else           { cp_wait<0>(); }
        __syncthreads();

        int buf = p & 1;
        u32 sa = sAbase + buf * ABUF;
        u32 sb = sBbase + buf * BBUF;

        #pragma unroll
        for (int k16 = 0; k16 < 32; k16 += 16) {
            u32 a[2][4];
            #pragma unroll
            for (int mi = 0; mi < 2; mi++)
                ldm_x4(a[mi][0], a[mi][1], a[mi][2], a[mi][3],
                       sa + (u32)((a_row + mi * 16) * 80 + (k16 + a_col) * 2));
            u32 b[4][4];
            #pragma unroll
            for (int g = 0; g < 4; g++)
                ldm_x4(b[g][0], b[g][1], b[g][2], b[g][3],
                       sb + (u32)((g * 16 + b_row) * 80 + (k16 + b_col) * 2));
            #pragma unroll
            for (int mi = 0; mi < 2; mi++)
                #pragma unroll
                for (int nf = 0; nf < 8; nf++) {
                    u32 bb0 = b[nf >> 1][(nf & 1) * 2];
                    u32 bb1 = b[nf >> 1][(nf & 1) * 2 + 1];
                    mma_bf16(acc[mi][nf][0], acc[mi][nf][1],
                             acc[mi][nf][2], acc[mi][nf][3],
                             a[mi][0], a[mi][1], a[mi][2], a[mi][3], bb0, bb1);
                }
        }
        __syncthreads();
    }

    const int gid = lane >> 2, tig = lane & 3;
    #pragma unroll
    for (int mi = 0; mi < 2; mi++) {
        int n0 = nb * 128 + warp * 32 + mi * 16 + gid;
        #pragma unroll
        for (int nf = 0; nf < 8; nf++) {
            int o = ob * 64 + nf * 8 + tig * 2;
            *(float2*)(Y + (size_t)n0 * Dout + o) =
                make_float2(acc[mi][nf][0], acc[mi][nf][1]);
            *(float2*)(Y + (size_t)(n0 + 8) * Dout + o) =
                make_float2(acc[mi][nf][2], acc[mi][nf][3]);
        }
    }
}

// ---------------- HMMA fused Based attention ------------------------------
// Block: 64 n-rows, 4 warps (16 rows each, all 64 e-cols). m in tiles of 32.
__global__ __launch_bounds__(128) void attn_mma()
{
    __shared__ __align__(16) __nv_bfloat16 Qs[64][56];       // [n][48]
    __shared__ __align__(16) __nv_bfloat16 Ks[2][32][56];    // [m][48]
    __shared__ __align__(16) __nv_bfloat16 Vs[2][128][40];   // [e(hi|lo)][m32]
    __shared__ __align__(16) __nv_bfloat16 Wh[64][40];       // [n][m32]
    __shared__ __align__(16) __nv_bfloat16 Wl[64][40];

    const int t = threadIdx.x, warp = t >> 5, lane = t & 31;
    const int rb = blockIdx.x, bh = blockIdx.y;
    const int b = bh / Hh, h = bh % Hh;
    const int gid = lane >> 2, tig = lane & 3;

    const __nv_bfloat16* Qb = g_qsp + ((size_t)bh * Ls + rb * 64) * 48;
    const __nv_bfloat16* Kb = g_ksp + (size_t)bh * Ls * 48;
    const __nv_bfloat16* Vb = g_vsp + (size_t)bh * 128 * Ls;

    const u32 sQ  = smem_u32(&Qs[0][0]);
    const u32 sK  = smem_u32(&Ks[0][0][0]);
    const u32 sV  = smem_u32(&Vs[0][0][0]);
    const u32 sWh = smem_u32(&Wh[0][0]);
    const u32 sWl = smem_u32(&Wl[0][0]);
    const u32 KBUF = 32 * 56 * 2, VBUF = 128 * 40 * 2;

    const int a_row = (lane & 7) + ((lane >> 3) & 1) * 8;
    const int a_col = ((lane >> 4) & 1) * 8;
    const int b_row = ((lane >> 4) & 1) * 8 + (lane & 7);
    const int b_col = ((lane >> 3) & 1) * 8;

    // Q tile: 64 rows x 6 vec16 = 384 vecs, 3/thread
    #pragma unroll
    for (int it = 0; it < 3; it++) {
        int idx = t + 128 * it;
        int r = idx / 6, j = idx % 6;
        cp_async16(sQ + (u32)(r * 112 + j * 16), Qb + (size_t)r * 48 + j * 8);
    }
    cp_commit();

    auto load_tile = [&](int mt, int buf) {
        const __nv_bfloat16* kp = Kb + (size_t)mt * 32 * 48;
        // K tile: 192 vecs
        #pragma unroll
        for (int it = 0; it < 2; it++) {
            int idx = t + 128 * it;
            if (idx < 192) {
                int r = idx / 6, j = idx % 6;
                cp_async16(sK + buf * KBUF + (u32)(r * 112 + j * 16),
                           kp + (size_t)r * 48 + j * 8);
            }
        }
        // V tile: 128 e-rows x 4 vec16 (32 m) = 512 vecs, 4/thread
        #pragma unroll
        for (int it = 0; it < 4; it++) {
            int idx = t + 128 * it;
            int r = idx >> 2, j = idx & 3;
            cp_async16(sV + buf * VBUF + (u32)(r * 80 + j * 16),
                       Vb + (size_t)r * Ls + mt * 32 + j * 8);
        }
        cp_commit();
    };

    load_tile(0, 0);
    cp_wait<0>();
    __syncthreads();

    // Q fragments (persistent): rows 16*warp.., K=48 -> 3 ksteps
    u32 aq[3][4];
    #pragma unroll
    for (int ks = 0; ks < 3; ks++)
        ldm_x4(aq[ks][0], aq[ks][1], aq[ks][2], aq[ks][3],
               sQ + (u32)((16 * warp + a_row) * 112 + (ks * 16 + a_col) * 2));

    float accy[8][4];
    #pragma unroll
    for (int eg = 0; eg < 8; eg++)
        #pragma unroll
        for (int j = 0; j < 4; j++) accy[eg][j] = 0.0f;
    float z0 = 0.0f, z1 = 0.0f;

    const int nA = rb * 64 + warp * 16 + gid;
    const int nB = nA + 8;
    const int nlA = warp * 16 + gid, nlB = nlA + 8;

    #pragma unroll 1
    for (int mt = 0; mt < NMT; mt++) {
        const int cur = mt & 1;
        if (mt + 1 < NMT) { load_tile(mt + 1, 1 - cur); cp_wait<1>(); }
        else              { cp_wait<0>(); }
        __syncthreads();

        // ---- phase A: S[16n x 32m] per warp ----
        float sacc[4][4];
        #pragma unroll
        for (int cg = 0; cg < 4; cg++)
            #pragma unroll
            for (int j = 0; j < 4; j++) sacc[cg][j] = 0.0f;
        #pragma unroll
        for (int ks = 0; ks < 3; ks++) {
            u32 kb[2][4];
            #pragma unroll
            for (int g = 0; g < 2; g++)
                ldm_x4(kb[g][0], kb[g][1], kb[g][2], kb[g][3],
                       sK + cur * KBUF +
                       (u32)((g * 16 + b_row) * 112 + (ks * 16 + b_col) * 2));
            #pragma unroll
            for (int cg = 0; cg < 4; cg++)
                mma_bf16(sacc[cg][0], sacc[cg][1], sacc[cg][2], sacc[cg][3],
                         aq[ks][0], aq[ks][1], aq[ks][2], aq[ks][3],
                         kb[cg >> 1][(cg & 1) * 2], kb[cg >> 1][(cg & 1) * 2 + 1]);
        }

        // ---- transform s -> w, split, store ----
        #pragma unroll
        for (int cg = 0; cg < 4; cg++) {
            int m0 = mt * 32 + cg * 8 + tig * 2;
            float s0 = sacc[cg][0], s1 = sacc[cg][1];
            float w0 = fmaf(s0, fmaf(s0, 0.03125f, 0.25f), 1.0f);
            float w1 = fmaf(s1, fmaf(s1, 0.03125f, 0.25f), 1.0f);
            if (m0     <= nA) w0 += w0;
            if (m0 + 1 <= nA) w1 += w1;
            z0 += w0 + w1;
            __nv_bfloat16 h0 = __float2bfloat16(w0), h1 = __float2bfloat16(w1);
            *(__nv_bfloat162*)&Wh[nlA][cg * 8 + tig * 2] = __halves2bfloat162(h0, h1);
            *(__nv_bfloat162*)&Wl[nlA][cg * 8 + tig * 2] = __halves2bfloat162(
                __float2bfloat16(w0 - __bfloat162float(h0)),
                __float2bfloat16(w1 - __bfloat162float(h1)));

            float s2 = sacc[cg][2], s3 = sacc[cg][3];
            float w2 = fmaf(s2, fmaf(s2, 0.03125f, 0.25f), 1.0f);
            float w3 = fmaf(s3, fmaf(s3, 0.03125f, 0.25f), 1.0f);
            if (m0     <= nB) w2 += w2;
            if (m0 + 1 <= nB) w3 += w3;
            z1 += w2 + w3;
            __nv_bfloat16 h2 = __float2bfloat16(w2), h3 = __float2bfloat16(w3);
            *(__nv_bfloat162*)&Wh[nlB][cg * 8 + tig * 2] = __halves2bfloat162(h2, h3);
            *(__nv_bfloat162*)&Wl[nlB][cg * 8 + tig * 2] = __halves2bfloat162(
                __float2bfloat16(w2 - __bfloat162float(h2)),
                __float2bfloat16(w3 - __bfloat162float(h3)));
        }
        __syncthreads();

        // ---- phase B: y += w*V (3-term), contraction 32m, V [e][m] -------
        #pragma unroll
        for (int c = 0; c < 2; c++) {
            u32 ah[4], al[4];
            ldm_x4(ah[0], ah[1], ah[2], ah[3],
                   sWh + (u32)((16 * warp + a_row) * 80 + (c * 16 + a_col) * 2));
            ldm_x4(al[0], al[1], al[2], al[3],
                   sWl + (u32)((16 * warp + a_row) * 80 + (c * 16 + a_col) * 2));
            u32 vh[4][4], vl[4][4];
            #pragma unroll
            for (int g = 0; g < 4; g++) {
                ldm_x4(vh[g][0], vh[g][1], vh[g][2], vh[g][3],
                       sV + cur * VBUF +
                       (u32)((g * 16 + b_row) * 80 + (c * 16 + b_col) * 2));
                ldm_x4(vl[g][0], vl[g][1], vl[g][2], vl[g][3],
                       sV + cur * VBUF + 64u * 80u +
                       (u32)((g * 16 + b_row) * 80 + (c * 16 + b_col) * 2));
            }
            #pragma unroll
            for (int eg = 0; eg < 8; eg++) {
                u32 bh0 = vh[eg >> 1][(eg & 1) * 2], bh1 = vh[eg >> 1][(eg & 1) * 2 + 1];
                u32 bl0 = vl[eg >> 1][(eg & 1) * 2], bl1 = vl[eg >> 1][(eg & 1) * 2 + 1];
                mma_bf16(accy[eg][0], accy[eg][1], accy[eg][2], accy[eg][3],
                         ah[0], ah[1], ah[2], ah[3], bh0, bh1);
                mma_bf16(accy[eg][0], accy[eg][1], accy[eg][2], accy[eg][3],
                         al[0], al[1], al[2], al[3], bh0, bh1);
                mma_bf16(accy[eg][0], accy[eg][1], accy[eg][2], accy[eg][3],
                         ah[0], ah[1], ah[2], ah[3], bl0, bl1);
            }
        }
        __syncthreads();
    }

    // ---- epilogue ----
    z0 += __shfl_xor_sync(0xFFFFFFFF, z0, 1);
    z0 += __shfl_xor_sync(0xFFFFFFFF, z0, 2);
    z1 += __shfl_xor_sync(0xFFFFFFFF, z1, 1);
    z1 += __shfl_xor_sync(0xFFFFFFFF, z1, 2);
    float rz0 = 1.0f / z0, rz1 = 1.0f / z1;

    float* yA = g_y + (size_t)(b * Ls + nA) * DM + h * HD;
    float* yB = g_y + (size_t)(b * Ls + nB) * DM + h * HD;
    #pragma unroll
    for (int eg = 0; eg < 8; eg++) {
        int e = eg * 8 + tig * 2;
        *(float2*)(yA + e) = make_float2(accy[eg][0] * rz0, accy[eg][1] * rz0);
        *(float2*)(yB + e) = make_float2(accy[eg][2] * rz1, accy[eg][3] * rz1);
    }
}

// ---------------- launcher ------------------------------------------------
extern "C" void kernel_launch(void* const* d_in, const int* in_sizes, int n_in,
                              void* d_out, int out_size)
{
    const float* hs = (const float*)d_in[0];
    const float* Wq = (const float*)d_in[1];
    const float* Wk = (const float*)d_in[2];
    const float* Wv = (const float*)d_in[3];
    const float* Wo = (const float*)d_in[4];
    float* out = (float*)d_out;

    float *pq, *pk, *pv, *py;
    __nv_bfloat16 *pxs, *pys, *pwq, *pwk, *pwv, *pwo, *pqs, *pks, *pvs;
    cudaGetSymbolAddress((void**)&pq,  g_q);
    cudaGetSymbolAddress((void**)&pk,  g_k);
    cudaGetSymbolAddress((void**)&pv,  g_v);
    cudaGetSymbolAddress((void**)&py,  g_y);
    cudaGetSymbolAddress((void**)&pxs, g_xs);
    cudaGetSymbolAddress((void**)&pys, g_ys);
    cudaGetSymbolAddress((void**)&pwq, g_wqs);
    cudaGetSymbolAddress((void**)&pwk, g_wks);
    cudaGetSymbolAddress((void**)&pwv, g_wvs);
    cudaGetSymbolAddress((void**)&pwo, g_wos);
    cudaGetSymbolAddress((void**)&pqs, g_qsp);
    cudaGetSymbolAddress((void**)&pks, g_ksp);
    cudaGetSymbolAddress((void**)&pvs, g_vsp);

    // operand splits for projection GEMMs
    split_bf16<<<(NR*192 + 255)/256, 256>>>(hs, pxs, NR*192, 1);
    split_bf16<<<(192*192 + 255)/256, 256>>>(Wq, pwq, 192*192, 0);
    split_bf16<<<(192*192 + 255)/256, 256>>>(Wk, pwk, 192*192, 0);
    split_bf16<<<(DM*192 + 255)/256, 256>>>(Wv, pwv, DM*192, 0);
    split_bf16<<<(DM*192 + 255)/256, 256>>>(Wo, pwo, DM*192, 0);

    // projections
    hmma_gemm<<<dim3(NR/128, (Hh*FEAT)/64, 2), 128>>>(pxs, pwq, pwk, pq, pk, Hh*FEAT);
    hmma_gemm<<<dim3(NR/128, DM/64, 1), 128>>>(pxs, pwv, pwv, pv, pv, DM);

    // head-major splits for attention
    split_qk_attn<<<(NR*Hh + 255)/256, 256>>>(pq, pqs, 1);
    split_qk_attn<<<(NR*Hh + 255)/256, 256>>>(pk, pks, 0);
    split_v_attn<<<(Bb*Hh*(Ls/8)*128 + 255)/256, 256>>>(pv, pvs);

    // fused attention on tensor cores
    attn_mma<<<dim3(Ls/64, Bb*Hh), 128>>>();

    // output projection
    split_bf16<<<(NR*192 + 255)/256, 256>>>(py, pys, NR*192, 1);
    hmma_gemm<<<dim3(NR/128, DM/64, 1), 128>>>(pys, pwo, pwo, out, out, DM);
}

// round 9
// speedup vs baseline: 2.5543x; 1.2274x over previous
#include <cuda_runtime.h>
#include <cuda_bf16.h>

typedef unsigned long long u64;
typedef unsigned int u32;
#define DEV __device__ __forceinline__

static constexpr int Bb   = 2;
static constexpr int Ls   = 2048;
static constexpr int DM   = 768;
static constexpr int Hh   = 12;
static constexpr int FEAT = 16;
static constexpr int HD   = 64;
static constexpr int NR   = Bb * Ls;   // 4096 rows
static constexpr int K3   = 3 * DM;    // 2304
static constexpr int NP   = K3 / 32;   // 72 k-panels
static constexpr int NMT  = Ls / 32;   // 64 attn m-tiles

// ---------------- scratch (device globals) --------------------------------
__device__ float g_q[NR * Hh * FEAT];
__device__ float g_k[NR * Hh * FEAT];
__device__ float g_v[NR * DM];
__device__ __nv_bfloat16 g_xs [NR * K3];
__device__ __nv_bfloat16 g_ys [NR * K3];
__device__ __nv_bfloat16 g_wqs[(Hh*FEAT) * K3];
__device__ __nv_bfloat16 g_wks[(Hh*FEAT) * K3];
__device__ __nv_bfloat16 g_wvs[DM * K3];
__device__ __nv_bfloat16 g_wos[DM * K3];
__device__ __nv_bfloat16 g_qsp[(size_t)Bb*Hh*Ls*48];   // [bh][l][hi|lo|hi]
__device__ __nv_bfloat16 g_ksp[(size_t)Bb*Hh*Ls*48];   // [bh][l][hi|hi|lo]
__device__ __nv_bfloat16 g_vsp[(size_t)Bb*Hh*128*Ls];  // [bh][r(64 hi|64 lo)][l]

// ---------------- helpers -------------------------------------------------
DEV u32 smem_u32(const void* p) {
    u32 a; asm("{ .reg .u64 t; cvta.to.shared.u64 t, %1; cvt.u32.u64 %0, t; }"
               : "=r"(a) : "l"(p));
    return a;
}
DEV void cp_async16(u32 saddr, const void* gaddr) {
    asm volatile("cp.async.cg.shared.global [%0], [%1], 16;"
                 :: "r"(saddr), "l"(gaddr) : "memory");
}
DEV void cp_commit() { asm volatile("cp.async.commit_group;" ::: "memory"); }
template<int N> DEV void cp_wait() {
    asm volatile("cp.async.wait_group %0;" :: "n"(N) : "memory");
}
DEV void ldm_x4(u32 &r0, u32 &r1, u32 &r2, u32 &r3, u32 addr) {
    asm volatile("ldmatrix.sync.aligned.m8n8.x4.shared.b16 {%0,%1,%2,%3}, [%4];"
                 : "=r"(r0), "=r"(r1), "=r"(r2), "=r"(r3) : "r"(addr));
}
DEV void mma_bf16(float &c0, float &c1, float &c2, float &c3,
                  u32 a0, u32 a1, u32 a2, u32 a3, u32 b0, u32 b1) {
    asm volatile(
        "mma.sync.aligned.m16n8k16.row.col.f32.bf16.bf16.f32 "
        "{%0,%1,%2,%3}, {%4,%5,%6,%7}, {%8,%9}, {%0,%1,%2,%3};"
        : "+f"(c0), "+f"(c1), "+f"(c2), "+f"(c3)
        : "r"(a0), "r"(a1), "r"(a2), "r"(a3), "r"(b0), "r"(b1));
}
DEV u32 packbf2(float a, float b) {
    __nv_bfloat162 p = __halves2bfloat162(__float2bfloat16(a), __float2bfloat16(b));
    return *(u32*)&p;
}

// ---------------- fp32 -> bf16 3-way split (GEMM operands) ----------------
__global__ void split_bf16(const float* __restrict__ src,
                           __nv_bfloat16* __restrict__ dst, int total4, int modeA)
{
    int idx = blockIdx.x * blockDim.x + threadIdx.x;
    if (idx >= total4) return;
    int r  = idx / 192;
    int c4 = idx % 192;
    float4 v = *(const float4*)(src + (size_t)r * 768 + c4 * 4);
    float vv[4] = {v.x, v.y, v.z, v.w};
    __nv_bfloat16 h[4], l[4];
    #pragma unroll
    for (int i = 0; i < 4; i++) {
        h[i] = __float2bfloat16(vv[i]);
        l[i] = __float2bfloat16(vv[i] - __bfloat162float(h[i]));
    }
    __nv_bfloat162 hp0 = {h[0], h[1]}, hp1 = {h[2], h[3]};
    __nv_bfloat162 lp0 = {l[0], l[1]}, lp1 = {l[2], l[3]};
    __nv_bfloat162* d0 = (__nv_bfloat162*)(dst + (size_t)r * K3 + c4 * 4);
    __nv_bfloat162* d1 = (__nv_bfloat162*)(dst + (size_t)r * K3 + 768 + c4 * 4);
    __nv_bfloat162* d2 = (__nv_bfloat162*)(dst + (size_t)r * K3 + 1536 + c4 * 4);
    d0[0] = hp0; d0[1] = hp1;
    if (modeA) { d1[0] = lp0; d1[1] = lp1; d2[0] = hp0; d2[1] = hp1; }
    else       { d1[0] = hp0; d1[1] = hp1; d2[0] = lp0; d2[1] = lp1; }
}

// ---------------- q&k split to head-major [bh][l][48], one launch ---------
__global__ void split_qk_attn(const float* __restrict__ srcq,
                              const float* __restrict__ srck,
                              __nv_bfloat16* __restrict__ dq,
                              __nv_bfloat16* __restrict__ dk)
{
    int idx = blockIdx.x * blockDim.x + threadIdx.x;
    if (idx >= 2 * NR * Hh) return;
    int which = idx >= NR * Hh;
    int id = which ? idx - NR * Hh : idx;
    const float* src = which ? srck : srcq;
    __nv_bfloat16* dst = which ? dk : dq;
    int modeA = which ? 0 : 1;

    int n = id / Hh, h = id % Hh;
    int b = n / Ls, l = n % Ls;
    const float* sp = src + (size_t)n * (Hh*FEAT) + h * FEAT;
    __nv_bfloat16 buf[48];
    #pragma unroll
    for (int i = 0; i < 16; i++) {
        float v = sp[i];
        __nv_bfloat16 hi = __float2bfloat16(v);
        __nv_bfloat16 lo = __float2bfloat16(v - __bfloat162float(hi));
        buf[i] = hi;
        if (modeA) { buf[16+i] = lo; buf[32+i] = hi; }
        else       { buf[16+i] = hi; buf[32+i] = lo; }
    }
    uint4* d = (uint4*)(dst + ((size_t)(b*Hh+h)*Ls + l) * 48);
    const uint4* s4 = (const uint4*)buf;
    #pragma unroll
    for (int i = 0; i < 6; i++) d[i] = s4[i];
}

// ---------------- v split TRANSPOSED: [bh][r=e(hi|lo)][l] -----------------
__global__ void split_v_attn(const float* __restrict__ src,
                             __nv_bfloat16* __restrict__ dst)
{
    int idx = blockIdx.x * blockDim.x + threadIdx.x;
    if (idx >= Bb * Hh * (Ls/8) * 128) return;
    int r   = idx & 127;
    int l8  = (idx >> 7) & (Ls/8 - 1);
    int bh  = idx >> (7 + 8);
    int b = bh / Hh, h = bh % Hh;
    int e = r & 63;
    bool low = r >= 64;

    __nv_bfloat16 outb[8];
    #pragma unroll
    for (int i = 0; i < 8; i++) {
        float v = src[((size_t)(b * Ls + l8 * 8 + i)) * DM + h * HD + e];
        __nv_bfloat16 hi = __float2bfloat16(v);
        outb[i] = low ? __float2bfloat16(v - __bfloat162float(hi)) : hi;
    }
    *(uint4*)(dst + ((size_t)bh * 128 + r) * Ls + l8 * 8) = *(const uint4*)outb;
}

// ---------------- HMMA NT GEMM body (proven R5) ---------------------------
DEV void gemm_body(const __nv_bfloat16* __restrict__ A,
                   const __nv_bfloat16* __restrict__ Bw,
                   float* __restrict__ Y, int Dout, int nb, int ob)
{
    __shared__ __align__(16) __nv_bfloat16 As[2][128][40];
    __shared__ __align__(16) __nv_bfloat16 Bs[2][64][40];

    const int t = threadIdx.x, warp = t >> 5, lane = t & 31;

    const __nv_bfloat16* Ab = A  + (size_t)nb * 128 * K3;
    const __nv_bfloat16* Bb = Bw + (size_t)ob * 64 * K3;

    float acc[2][8][4];
    #pragma unroll
    for (int mi = 0; mi < 2; mi++)
        #pragma unroll
        for (int nf = 0; nf < 8; nf++)
            #pragma unroll
            for (int j = 0; j < 4; j++) acc[mi][nf][j] = 0.0f;

    const int ar = t >> 2, ac = t & 3;
    const int a_row = warp * 32 + (lane & 7) + ((lane >> 3) & 1) * 8;
    const int a_col = ((lane >> 4) & 1) * 8;
    const int b_row = ((lane >> 4) & 1) * 8 + (lane & 7);
    const int b_col = ((lane >> 3) & 1) * 8;

    u32 sAbase = smem_u32(&As[0][0][0]);
    u32 sBbase = smem_u32(&Bs[0][0][0]);
    const u32 ABUF = 128 * 40 * 2, BBUF = 64 * 40 * 2;

    auto load_panel = [&](int p, int buf) {
        int kp = p * 32;
        u32 sa = sAbase + buf * ABUF;
        u32 sb = sBbase + buf * BBUF;
        #pragma unroll
        for (int it = 0; it < 4; it++) {
            int r = ar + 32 * it;
            cp_async16(sa + (u32)(r * 80 + ac * 16),
                       Ab + (size_t)r * K3 + kp + ac * 8);
        }
        #pragma unroll
        for (int it = 0; it < 2; it++) {
            int r = ar + 32 * it;
            cp_async16(sb + (u32)(r * 80 + ac * 16),
                       Bb + (size_t)r * K3 + kp + ac * 8);
        }
        cp_commit();
    };

    load_panel(0, 0);

    for (int p = 0; p < NP; p++) {
        if (p + 1 < NP) { load_panel(p + 1, (p + 1) & 1); cp_wait<1>(); }
        else           { cp_wait<0>(); }
        __syncthreads();

        int buf = p & 1;
        u32 sa = sAbase + buf * ABUF;
        u32 sb = sBbase + buf * BBUF;

        #pragma unroll
        for (int k16 = 0; k16 < 32; k16 += 16) {
            u32 a[2][4];
            #pragma unroll
            for (int mi = 0; mi < 2; mi++)
                ldm_x4(a[mi][0], a[mi][1], a[mi][2], a[mi][3],
                       sa + (u32)((a_row + mi * 16) * 80 + (k16 + a_col) * 2));
            u32 b[4][4];
            #pragma unroll
            for (int g = 0; g < 4; g++)
                ldm_x4(b[g][0], b[g][1], b[g][2], b[g][3],
                       sb + (u32)((g * 16 + b_row) * 80 + (k16 + b_col) * 2));
            #pragma unroll
            for (int mi = 0; mi < 2; mi++)
                #pragma unroll
                for (int nf = 0; nf < 8; nf++) {
                    u32 bb0 = b[nf >> 1][(nf & 1) * 2];
                    u32 bb1 = b[nf >> 1][(nf & 1) * 2 + 1];
                    mma_bf16(acc[mi][nf][0], acc[mi][nf][1],
                             acc[mi][nf][2], acc[mi][nf][3],
                             a[mi][0], a[mi][1], a[mi][2], a[mi][3], bb0, bb1);
                }
        }
        __syncthreads();
    }

    const int gid = lane >> 2, tig = lane & 3;
    #pragma unroll
    for (int mi = 0; mi < 2; mi++) {
        int n0 = nb * 128 + warp * 32 + mi * 16 + gid;
        #pragma unroll
        for (int nf = 0; nf < 8; nf++) {
            int o = ob * 64 + nf * 8 + tig * 2;
            *(float2*)(Y + (size_t)n0 * Dout + o) =
                make_float2(acc[mi][nf][0], acc[mi][nf][1]);
            *(float2*)(Y + (size_t)(n0 + 8) * Dout + o) =
                make_float2(acc[mi][nf][2], acc[mi][nf][3]);
        }
    }
}

// one kernel serving q/k/v merged (t1=3,t2=6) or Wo (t1=t2=0 -> third branch)
__global__ __launch_bounds__(128) void hmma_gemm3(
    const __nv_bfloat16* __restrict__ A,
    const __nv_bfloat16* __restrict__ B0, const __nv_bfloat16* __restrict__ B1,
    const __nv_bfloat16* __restrict__ B2,
    float* __restrict__ Y0, float* __restrict__ Y1, float* __restrict__ Y2,
    int t1, int t2, int D01, int D2)
{
    int ob = blockIdx.y;
    const __nv_bfloat16* Bw; float* Y; int D, obl;
    if (ob < t1)      { Bw = B0; Y = Y0; D = D01; obl = ob; }
    else if (ob < t2) { Bw = B1; Y = Y1; D = D01; obl = ob - t1; }
    else              { Bw = B2; Y = Y2; D = D2;  obl = ob - t2; }
    gemm_body(A, Bw, Y, D, blockIdx.x, obl);
}

// ---------------- HMMA fused Based attention (register-passing) -----------
// Block: 64 n-rows, 4 warps (16 rows each). m in tiles of 32. No W smem.
__global__ __launch_bounds__(128, 4) void attn_mma()
{
    __shared__ __align__(16) __nv_bfloat16 Qs[64][56];       // [n][48]
    __shared__ __align__(16) __nv_bfloat16 Ks[2][32][56];    // [m][48]
    __shared__ __align__(16) __nv_bfloat16 Vs[2][128][40];   // [e(hi|lo)][m32]

    const int t = threadIdx.x, warp = t >> 5, lane = t & 31;
    const int rb = blockIdx.x, bh = blockIdx.y;
    const int b = bh / Hh, h = bh % Hh;
    const int gid = lane >> 2, tig = lane & 3;

    const __nv_bfloat16* Qb = g_qsp + ((size_t)bh * Ls + rb * 64) * 48;
    const __nv_bfloat16* Kb = g_ksp + (size_t)bh * Ls * 48;
    const __nv_bfloat16* Vb = g_vsp + (size_t)bh * 128 * Ls;

    const u32 sQ  = smem_u32(&Qs[0][0]);
    const u32 sK  = smem_u32(&Ks[0][0][0]);
    const u32 sV  = smem_u32(&Vs[0][0][0]);
    const u32 KBUF = 32 * 56 * 2, VBUF = 128 * 40 * 2;

    const int a_row = (lane & 7) + ((lane >> 3) & 1) * 8;
    const int a_col = ((lane >> 4) & 1) * 8;
    const int b_row = ((lane >> 4) & 1) * 8 + (lane & 7);
    const int b_col = ((lane >> 3) & 1) * 8;

    // Q tile: 64 rows x 6 vec16 = 384 vecs, 3/thread
    #pragma unroll
    for (int it = 0; it < 3; it++) {
        int idx = t + 128 * it;
        int r = idx / 6, j = idx % 6;
        cp_async16(sQ + (u32)(r * 112 + j * 16), Qb + (size_t)r * 48 + j * 8);
    }
    cp_commit();

    auto load_tile = [&](int mt, int buf) {
        const __nv_bfloat16* kp = Kb + (size_t)mt * 32 * 48;
        #pragma unroll
        for (int it = 0; it < 2; it++) {
            int idx = t + 128 * it;
            if (idx < 192) {
                int r = idx / 6, j = idx % 6;
                cp_async16(sK + buf * KBUF + (u32)(r * 112 + j * 16),
                           kp + (size_t)r * 48 + j * 8);
            }
        }
        #pragma unroll
        for (int it = 0; it < 4; it++) {
            int idx = t + 128 * it;
            int r = idx >> 2, j = idx & 3;
            cp_async16(sV + buf * VBUF + (u32)(r * 80 + j * 16),
                       Vb + (size_t)r * Ls + mt * 32 + j * 8);
        }
        cp_commit();
    };

    load_tile(0, 0);
    cp_wait<0>();
    __syncthreads();

    u32 aq[3][4];
    #pragma unroll
    for (int ks = 0; ks < 3; ks++)
        ldm_x4(aq[ks][0], aq[ks][1], aq[ks][2], aq[ks][3],
               sQ + (u32)((16 * warp + a_row) * 112 + (ks * 16 + a_col) * 2));

    float accy[8][4];
    #pragma unroll
    for (int eg = 0; eg < 8; eg++)
        #pragma unroll
        for (int j = 0; j < 4; j++) accy[eg][j] = 0.0f;
    float z0 = 0.0f, z1 = 0.0f;

    const int nA = rb * 64 + warp * 16 + gid;
    const int nB = nA + 8;

    #pragma unroll 1
    for (int mt = 0; mt < NMT; mt++) {
        const int cur = mt & 1;
        if (mt + 1 < NMT) { load_tile(mt + 1, 1 - cur); cp_wait<1>(); }
        else              { cp_wait<0>(); }
        __syncthreads();

        // ---- phase A: S[16n x 32m] per warp ----
        float sacc[4][4];
        #pragma unroll
        for (int cg = 0; cg < 4; cg++)
            #pragma unroll
            for (int j = 0; j < 4; j++) sacc[cg][j] = 0.0f;
        #pragma unroll
        for (int ks = 0; ks < 3; ks++) {
            u32 kb[2][4];
            #pragma unroll
            for (int g = 0; g < 2; g++)
                ldm_x4(kb[g][0], kb[g][1], kb[g][2], kb[g][3],
                       sK + cur * KBUF +
                       (u32)((g * 16 + b_row) * 112 + (ks * 16 + b_col) * 2));
            #pragma unroll
            for (int cg = 0; cg < 4; cg++)
                mma_bf16(sacc[cg][0], sacc[cg][1], sacc[cg][2], sacc[cg][3],
                         aq[ks][0], aq[ks][1], aq[ks][2], aq[ks][3],
                         kb[cg >> 1][(cg & 1) * 2], kb[cg >> 1][(cg & 1) * 2 + 1]);
        }

        // ---- transform s -> w in registers, pack into phase-B A-frags ----
        // C-frag (gid,2tig|2tig+1 / gid+8,...) maps exactly onto A-frag rows
        // gid/gid+8 x kcols 2tig/2tig+8 (FA2 register passing).
        u32 ah[2][4], al[2][4];
        #pragma unroll
        for (int cg = 0; cg < 4; cg++) {
            int m0 = mt * 32 + cg * 8 + tig * 2;
            float w0 = fmaf(sacc[cg][0], fmaf(sacc[cg][0], 0.03125f, 0.25f), 1.0f);
            float w1 = fmaf(sacc[cg][1], fmaf(sacc[cg][1], 0.03125f, 0.25f), 1.0f);
            float w2 = fmaf(sacc[cg][2], fmaf(sacc[cg][2], 0.03125f, 0.25f), 1.0f);
            float w3 = fmaf(sacc[cg][3], fmaf(sacc[cg][3], 0.03125f, 0.25f), 1.0f);
            if (m0     <= nA) w0 += w0;
            if (m0 + 1 <= nA) w1 += w1;
            if (m0     <= nB) w2 += w2;
            if (m0 + 1 <= nB) w3 += w3;
            z0 += w0 + w1;
            z1 += w2 + w3;
            __nv_bfloat16 h0 = __float2bfloat16(w0), h1 = __float2bfloat16(w1);
            __nv_bfloat16 h2 = __float2bfloat16(w2), h3 = __float2bfloat16(w3);
            int c = cg >> 1, q = cg & 1;
            __nv_bfloat162 ph01 = {h0, h1}, ph23 = {h2, h3};
            ah[c][q * 2]     = *(u32*)&ph01;
            ah[c][q * 2 + 1] = *(u32*)&ph23;
            __nv_bfloat162 pl01 = {__float2bfloat16(w0 - __bfloat162float(h0)),
                                   __float2bfloat16(w1 - __bfloat162float(h1))};
            __nv_bfloat162 pl23 = {__float2bfloat16(w2 - __bfloat162float(h2)),
                                   __float2bfloat16(w3 - __bfloat162float(h3))};
            al[c][q * 2]     = *(u32*)&pl01;
            al[c][q * 2 + 1] = *(u32*)&pl23;
        }

        // ---- phase B: y += w*V (3-term), contraction 32m, V [e][m] -------
        #pragma unroll
        for (int c = 0; c < 2; c++) {
            u32 vh[4][4], vl[4][4];
            #pragma unroll
            for (int g = 0; g < 4; g++) {
                ldm_x4(vh[g][0], vh[g][1], vh[g][2], vh[g][3],
                       sV + cur * VBUF +
                       (u32)((g * 16 + b_row) * 80 + (c * 16 + b_col) * 2));
                ldm_x4(vl[g][0], vl[g][1], vl[g][2], vl[g][3],
                       sV + cur * VBUF + 64u * 80u +
                       (u32)((g * 16 + b_row) * 80 + (c * 16 + b_col) * 2));
            }
            #pragma unroll
            for (int eg = 0; eg < 8; eg++) {
                u32 bh0 = vh[eg >> 1][(eg & 1) * 2], bh1 = vh[eg >> 1][(eg & 1) * 2 + 1];
                u32 bl0 = vl[eg >> 1][(eg & 1) * 2], bl1 = vl[eg >> 1][(eg & 1) * 2 + 1];
                mma_bf16(accy[eg][0], accy[eg][1], accy[eg][2], accy[eg][3],
                         ah[c][0], ah[c][1], ah[c][2], ah[c][3], bh0, bh1);
                mma_bf16(accy[eg][0], accy[eg][1], accy[eg][2], accy[eg][3],
                         al[c][0], al[c][1], al[c][2], al[c][3], bh0, bh1);
                mma_bf16(accy[eg][0], accy[eg][1], accy[eg][2], accy[eg][3],
                         ah[c][0], ah[c][1], ah[c][2], ah[c][3], bl0, bl1);
            }
        }
        __syncthreads();
    }

    // ---- epilogue: reduce denominators, scale, write split ys directly ---
    z0 += __shfl_xor_sync(0xFFFFFFFF, z0, 1);
    z0 += __shfl_xor_sync(0xFFFFFFFF, z0, 2);
    z1 += __shfl_xor_sync(0xFFFFFFFF, z1, 1);
    z1 += __shfl_xor_sync(0xFFFFFFFF, z1, 2);
    float rz0 = 1.0f / z0, rz1 = 1.0f / z1;

    __nv_bfloat16* yA = g_ys + (size_t)(b * Ls + nA) * K3 + h * HD;
    __nv_bfloat16* yB = g_ys + (size_t)(b * Ls + nB) * K3 + h * HD;
    #pragma unroll
    for (int eg = 0; eg < 8; eg++) {
        int e = eg * 8 + tig * 2;
        float y0 = accy[eg][0] * rz0, y1 = accy[eg][1] * rz0;
        float y2 = accy[eg][2] * rz1, y3 = accy[eg][3] * rz1;
        __nv_bfloat16 h0 = __float2bfloat16(y0), h1 = __float2bfloat16(y1);
        __nv_bfloat16 h2 = __float2bfloat16(y2), h3 = __float2bfloat16(y3);
        __nv_bfloat162 hA = {h0, h1}, hB = {h2, h3};
        __nv_bfloat162 lA = {__float2bfloat16(y0 - __bfloat162float(h0)),
                             __float2bfloat16(y1 - __bfloat162float(h1))};
        __nv_bfloat162 lB = {__float2bfloat16(y2 - __bfloat162float(h2)),
                             __float2bfloat16(y3 - __bfloat162float(h3))};
        *(__nv_bfloat162*)(yA + e)        = hA;   // hi
        *(__nv_bfloat162*)(yA + 768 + e)  = lA;   // lo
        *(__nv_bfloat162*)(yA + 1536 + e) = hA;   // hi
        *(__nv_bfloat162*)(yB + e)        = hB;
        *(__nv_bfloat162*)(yB + 768 + e)  = lB;
        *(__nv_bfloat162*)(yB + 1536 + e) = hB;
    }
}

// ---------------- launcher ------------------------------------------------
extern "C" void kernel_launch(void* const* d_in, const int* in_sizes, int n_in,
                              void* d_out, int out_size)
{
    const float* hs = (const float*)d_in[0];
    const float* Wq = (const float*)d_in[1];
    const float* Wk = (const float*)d_in[2];
    const float* Wv = (const float*)d_in[3];
    const float* Wo = (const float*)d_in[4];
    float* out = (float*)d_out;

    float *pq, *pk, *pv;
    __nv_bfloat16 *pxs, *pys, *pwq, *pwk, *pwv, *pwo, *pqs, *pks, *pvs;
    cudaGetSymbolAddress((void**)&pq,  g_q);
    cudaGetSymbolAddress((void**)&pk,  g_k);
    cudaGetSymbolAddress((void**)&pv,  g_v);
    cudaGetSymbolAddress((void**)&pxs, g_xs);
    cudaGetSymbolAddress((void**)&pys, g_ys);
    cudaGetSymbolAddress((void**)&pwq, g_wqs);
    cudaGetSymbolAddress((void**)&pwk, g_wks);
    cudaGetSymbolAddress((void**)&pwv, g_wvs);
    cudaGetSymbolAddress((void**)&pwo, g_wos);
    cudaGetSymbolAddress((void**)&pqs, g_qsp);
    cudaGetSymbolAddress((void**)&pks, g_ksp);
    cudaGetSymbolAddress((void**)&pvs, g_vsp);

    // operand splits for projection GEMMs
    split_bf16<<<(NR*192 + 255)/256, 256>>>(hs, pxs, NR*192, 1);
    split_bf16<<<(192*192 + 255)/256, 256>>>(Wq, pwq, 192*192, 0);
    split_bf16<<<(192*192 + 255)/256, 256>>>(Wk, pwk, 192*192, 0);
    split_bf16<<<(DM*192 + 255)/256, 256>>>(Wv, pwv, DM*192, 0);
    split_bf16<<<(DM*192 + 255)/256, 256>>>(Wo, pwo, DM*192, 0);

    // q,k,v projections in one launch (32 x 18 tiles)
    hmma_gemm3<<<dim3(NR/128, 18), 128>>>(pxs, pwq, pwk, pwv, pq, pk, pv,
                                          3, 6, 192, 768);

    // head-major splits for attention
    split_qk_attn<<<(2*NR*Hh + 255)/256, 256>>>(pq, pk, pqs, pks);
    split_v_attn<<<(Bb*Hh*(Ls/8)*128 + 255)/256, 256>>>(pv, pvs);

    // fused attention on tensor cores (writes split ys directly)
    attn_mma<<<dim3(Ls/64, Bb*Hh), 128>>>();

    // output projection
    hmma_gemm3<<<dim3(NR/128, 12), 128>>>(pys, pwo, pwo, pwo, out, out, out,
                                          0, 0, 768, 768);
}

// round 12
// speedup vs baseline: 2.5711x; 1.0066x over previous
#include <cuda_runtime.h>
#include <cuda_bf16.h>

typedef unsigned long long u64;
typedef unsigned int u32;
#define DEV __device__ __forceinline__

static constexpr int Bb   = 2;
static constexpr int Ls   = 2048;
static constexpr int DM   = 768;
static constexpr int Hh   = 12;
static constexpr int FEAT = 16;
static constexpr int HD   = 64;
static constexpr int NR   = Bb * Ls;   // 4096 rows
static constexpr int K3   = 3 * DM;    // 2304
static constexpr int NP   = K3 / 32;   // 72 k-panels
static constexpr int NMT  = Ls / 32;   // 64 attn m-tiles

// ---------------- scratch (device globals) --------------------------------
__device__ float g_v[NR * DM];
__device__ __nv_bfloat16 g_xs [NR * K3];
__device__ __nv_bfloat16 g_ys [NR * K3];
__device__ __nv_bfloat16 g_wqs[(Hh*FEAT) * K3];
__device__ __nv_bfloat16 g_wks[(Hh*FEAT) * K3];
__device__ __nv_bfloat16 g_wvs[DM * K3];
__device__ __nv_bfloat16 g_wos[DM * K3];
__device__ __nv_bfloat16 g_qsp[(size_t)Bb*Hh*Ls*48];   // [bh][l][hi|lo|hi]
__device__ __nv_bfloat16 g_ksp[(size_t)Bb*Hh*Ls*48];   // [bh][l][hi|hi|lo]
__device__ __nv_bfloat16 g_vsp[(size_t)Bb*Hh*128*Ls];  // [bh][r(64 hi|64 lo)][l]

// ---------------- helpers -------------------------------------------------
DEV u32 smem_u32(const void* p) {
    u32 a; asm("{ .reg .u64 t; cvta.to.shared.u64 t, %1; cvt.u32.u64 %0, t; }"
               : "=r"(a) : "l"(p));
    return a;
}
DEV void cp_async16(u32 saddr, const void* gaddr) {
    asm volatile("cp.async.cg.shared.global [%0], [%1], 16;"
                 :: "r"(saddr), "l"(gaddr) : "memory");
}
DEV void cp_commit() { asm volatile("cp.async.commit_group;" ::: "memory"); }
template<int N> DEV void cp_wait() {
    asm volatile("cp.async.wait_group %0;" :: "n"(N) : "memory");
}
DEV void ldm_x4(u32 &r0, u32 &r1, u32 &r2, u32 &r3, u32 addr) {
    asm volatile("ldmatrix.sync.aligned.m8n8.x4.shared.b16 {%0,%1,%2,%3}, [%4];"
                 : "=r"(r0), "=r"(r1), "=r"(r2), "=r"(r3) : "r"(addr));
}
DEV void mma_bf16(float &c0, float &c1, float &c2, float &c3,
                  u32 a0, u32 a1, u32 a2, u32 a3, u32 b0, u32 b1) {
    asm volatile(
        "mma.sync.aligned.m16n8k16.row.col.f32.bf16.bf16.f32 "
        "{%0,%1,%2,%3}, {%4,%5,%6,%7}, {%8,%9}, {%0,%1,%2,%3};"
        : "+f"(c0), "+f"(c1), "+f"(c2), "+f"(c3)
        : "r"(a0), "r"(a1), "r"(a2), "r"(a3), "r"(b0), "r"(b1));
}

// ---------------- fp32 -> bf16 3-way split (A operands, mode [hi|lo|hi]) --
__global__ void split_bf16(const float* __restrict__ src,
                           __nv_bfloat16* __restrict__ dst, int total4, int modeA)
{
    int idx = blockIdx.x * blockDim.x + threadIdx.x;
    if (idx >= total4) return;
    int r  = idx / 192;
    int c4 = idx % 192;
    float4 v = *(const float4*)(src + (size_t)r * 768 + c4 * 4);
    float vv[4] = {v.x, v.y, v.z, v.w};
    __nv_bfloat16 h[4], l[4];
    #pragma unroll
    for (int i = 0; i < 4; i++) {
        h[i] = __float2bfloat16(vv[i]);
        l[i] = __float2bfloat16(vv[i] - __bfloat162float(h[i]));
    }
    __nv_bfloat162 hp0 = {h[0], h[1]}, hp1 = {h[2], h[3]};
    __nv_bfloat162 lp0 = {l[0], l[1]}, lp1 = {l[2], l[3]};
    __nv_bfloat162* d0 = (__nv_bfloat162*)(dst + (size_t)r * K3 + c4 * 4);
    __nv_bfloat162* d1 = (__nv_bfloat162*)(dst + (size_t)r * K3 + 768 + c4 * 4);
    __nv_bfloat162* d2 = (__nv_bfloat162*)(dst + (size_t)r * K3 + 1536 + c4 * 4);
    d0[0] = hp0; d0[1] = hp1;
    if (modeA) { d1[0] = lp0; d1[1] = lp1; d2[0] = hp0; d2[1] = hp1; }
    else       { d1[0] = hp0; d1[1] = hp1; d2[0] = lp0; d2[1] = lp1; }
}

// two weight splits in one launch (mode 0: [hi|hi|lo])
__global__ void split_w2(const float* __restrict__ s0, const float* __restrict__ s1,
                         __nv_bfloat16* __restrict__ d0b, __nv_bfloat16* __restrict__ d1b,
                         int per)
{
    int idx = blockIdx.x * blockDim.x + threadIdx.x;
    if (idx >= 2 * per) return;
    const float* src = (idx < per) ? s0 : s1;
    __nv_bfloat16* dst = (idx < per) ? d0b : d1b;
    int id = (idx < per) ? idx : idx - per;
    int r  = id / 192;
    int c4 = id % 192;
    float4 v = *(const float4*)(src + (size_t)r * 768 + c4 * 4);
    float vv[4] = {v.x, v.y, v.z, v.w};
    __nv_bfloat16 h[4], l[4];
    #pragma unroll
    for (int i = 0; i < 4; i++) {
        h[i] = __float2bfloat16(vv[i]);
        l[i] = __float2bfloat16(vv[i] - __bfloat162float(h[i]));
    }
    __nv_bfloat162 hp0 = {h[0], h[1]}, hp1 = {h[2], h[3]};
    __nv_bfloat162 lp0 = {l[0], l[1]}, lp1 = {l[2], l[3]};
    __nv_bfloat162* o0 = (__nv_bfloat162*)(dst + (size_t)r * K3 + c4 * 4);
    __nv_bfloat162* o1 = (__nv_bfloat162*)(dst + (size_t)r * K3 + 768 + c4 * 4);
    __nv_bfloat162* o2 = (__nv_bfloat162*)(dst + (size_t)r * K3 + 1536 + c4 * 4);
    o0[0] = hp0; o0[1] = hp1;
    o1[0] = hp0; o1[1] = hp1;
    o2[0] = lp0; o2[1] = lp1;
}

// ---------------- v split TRANSPOSED: [bh][r=e(hi|lo)][l] -----------------
__global__ void split_v_attn()
{
    int idx = blockIdx.x * blockDim.x + threadIdx.x;
    if (idx >= Bb * Hh * (Ls/8) * 128) return;
    int r   = idx & 127;
    int l8  = (idx >> 7) & (Ls/8 - 1);
    int bh  = idx >> (7 + 8);
    int b = bh / Hh, h = bh % Hh;
    int e = r & 63;
    bool low = r >= 64;

    __nv_bfloat16 outb[8];
    #pragma unroll
    for (int i = 0; i < 8; i++) {
        float v = g_v[((size_t)(b * Ls + l8 * 8 + i)) * DM + h * HD + e];
        __nv_bfloat16 hi = __float2bfloat16(v);
        outb[i] = low ? __float2bfloat16(v - __bfloat162float(hi)) : hi;
    }
    *(uint4*)(g_vsp + ((size_t)bh * 128 + r) * Ls + l8 * 8) = *(const uint4*)outb;
}

// ---------------- HMMA NT GEMM body with fused epilogues ------------------
// epi 0: fp32 Y[n, ob*64+o].  epi 1/2: write split q/k head-major bf16.
DEV void gemm_body(const __nv_bfloat16* __restrict__ A,
                   const __nv_bfloat16* __restrict__ Bw,
                   int nb, int ob, int epi,
                   float* __restrict__ Yf, int Dout,
                   __nv_bfloat16* __restrict__ Ybf)
{
    __shared__ __align__(16) __nv_bfloat16 As[2][128][40];
    __shared__ __align__(16) __nv_bfloat16 Bs[2][64][40];

    const int t = threadIdx.x, warp = t >> 5, lane = t & 31;

    const __nv_bfloat16* Ab = A  + (size_t)nb * 128 * K3;
    const __nv_bfloat16* Bb = Bw + (size_t)ob * 64 * K3;

    float acc[2][8][4];
    #pragma unroll
    for (int mi = 0; mi < 2; mi++)
        #pragma unroll
        for (int nf = 0; nf < 8; nf++)
            #pragma unroll
            for (int j = 0; j < 4; j++) acc[mi][nf][j] = 0.0f;

    const int ar = t >> 2, ac = t & 3;
    const int a_row = warp * 32 + (lane & 7) + ((lane >> 3) & 1) * 8;
    const int a_col = ((lane >> 4) & 1) * 8;
    const int b_row = ((lane >> 4) & 1) * 8 + (lane & 7);
    const int b_col = ((lane >> 3) & 1) * 8;

    u32 sAbase = smem_u32(&As[0][0][0]);
    u32 sBbase = smem_u32(&Bs[0][0][0]);
    const u32 ABUF = 128 * 40 * 2, BBUF = 64 * 40 * 2;

    auto load_panel = [&](int p, int buf) {
        int kp = p * 32;
        u32 sa = sAbase + buf * ABUF;
        u32 sb = sBbase + buf * BBUF;
        #pragma unroll
        for (int it = 0; it < 4; it++) {
            int r = ar + 32 * it;
            cp_async16(sa + (u32)(r * 80 + ac * 16),
                       Ab + (size_t)r * K3 + kp + ac * 8);
        }
        #pragma unroll
        for (int it = 0; it < 2; it++) {
            int r = ar + 32 * it;
            cp_async16(sb + (u32)(r * 80 + ac * 16),
                       Bb + (size_t)r * K3 + kp + ac * 8);
        }
        cp_commit();
    };

    load_panel(0, 0);

    for (int p = 0; p < NP; p++) {
        if (p + 1 < NP) { load_panel(p + 1, (p + 1) & 1); cp_wait<1>(); }
        else           { cp_wait<0>(); }
        __syncthreads();

        int buf = p & 1;
        u32 sa = sAbase + buf * ABUF;
        u32 sb = sBbase + buf * BBUF;

        #pragma unroll
        for (int k16 = 0; k16 < 32; k16 += 16) {
            u32 a[2][4];
            #pragma unroll
            for (int mi = 0; mi < 2; mi++)
                ldm_x4(a[mi][0], a[mi][1], a[mi][2], a[mi][3],
                       sa + (u32)((a_row + mi * 16) * 80 + (k16 + a_col) * 2));
            u32 b[4][4];
            #pragma unroll
            for (int g = 0; g < 4; g++)
                ldm_x4(b[g][0], b[g][1], b[g][2], b[g][3],
                       sb + (u32)((g * 16 + b_row) * 80 + (k16 + b_col) * 2));
            #pragma unroll
            for (int mi = 0; mi < 2; mi++)
                #pragma unroll
                for (int nf = 0; nf < 8; nf++) {
                    u32 bb0 = b[nf >> 1][(nf & 1) * 2];
                    u32 bb1 = b[nf >> 1][(nf & 1) * 2 + 1];
                    mma_bf16(acc[mi][nf][0], acc[mi][nf][1],
                             acc[mi][nf][2], acc[mi][nf][3],
                             a[mi][0], a[mi][1], a[mi][2], a[mi][3], bb0, bb1);
                }
        }
        __syncthreads();
    }

    const int gid = lane >> 2, tig = lane & 3;
    if (epi == 0) {
        #pragma unroll
        for (int mi = 0; mi < 2; mi++) {
            int n0 = nb * 128 + warp * 32 + mi * 16 + gid;
            #pragma unroll
            for (int nf = 0; nf < 8; nf++) {
                int o = ob * 64 + nf * 8 + tig * 2;
                *(float2*)(Yf + (size_t)n0 * Dout + o) =
                    make_float2(acc[mi][nf][0], acc[mi][nf][1]);
                *(float2*)(Yf + (size_t)(n0 + 8) * Dout + o) =
                    make_float2(acc[mi][nf][2], acc[mi][nf][3]);
            }
        }
    } else {
        // split head-major write: o = h*16 + f ; row n -> (b, l)
        #pragma unroll
        for (int mi = 0; mi < 2; mi++) {
            int n0 = nb * 128 + warp * 32 + mi * 16 + gid;
            int b = n0 >> 11;
            int l = n0 & (Ls - 1);
            #pragma unroll
            for (int nf = 0; nf < 8; nf++) {
                int o = ob * 64 + nf * 8 + tig * 2;
                int h = o >> 4, f = o & 15;
                __nv_bfloat16* dr0 = Ybf + ((size_t)(b * Hh + h) * Ls + l) * 48;
                __nv_bfloat16* dr1 = dr0 + 8 * 48;
                float y0 = acc[mi][nf][0], y1 = acc[mi][nf][1];
                float y2 = acc[mi][nf][2], y3 = acc[mi][nf][3];
                __nv_bfloat16 h0 = __float2bfloat16(y0), h1 = __float2bfloat16(y1);
                __nv_bfloat16 h2 = __float2bfloat16(y2), h3 = __float2bfloat16(y3);
                __nv_bfloat162 hi0 = {h0, h1}, hi1 = {h2, h3};
                __nv_bfloat162 lo0 = {__float2bfloat16(y0 - __bfloat162float(h0)),
                                      __float2bfloat16(y1 - __bfloat162float(h1))};
                __nv_bfloat162 lo1 = {__float2bfloat16(y2 - __bfloat162float(h2)),
                                      __float2bfloat16(y3 - __bfloat162float(h3))};
                *(__nv_bfloat162*)(dr0 + f) = hi0;
                *(__nv_bfloat162*)(dr1 + f) = hi1;
                if (epi == 1) {   // q: [hi|lo|hi]
                    *(__nv_bfloat162*)(dr0 + 16 + f) = lo0;
                    *(__nv_bfloat162*)(dr1 + 16 + f) = lo1;
                    *(__nv_bfloat162*)(dr0 + 32 + f) = hi0;
                    *(__nv_bfloat162*)(dr1 + 32 + f) = hi1;
                } else {          // k: [hi|hi|lo]
                    *(__nv_bfloat162*)(dr0 + 16 + f) = hi0;
                    *(__nv_bfloat162*)(dr1 + 16 + f) = hi1;
                    *(__nv_bfloat162*)(dr0 + 32 + f) = lo0;
                    *(__nv_bfloat162*)(dr1 + 32 + f) = lo1;
                }
            }
        }
    }
}

// q/k/v projections in one launch; q,k write split head-major directly.
__global__ __launch_bounds__(128) void hmma_qkv()
{
    int ob = blockIdx.y;
    if (ob < 3)
        gemm_body(g_xs, g_wqs, blockIdx.x, ob, 1, nullptr, 0, g_qsp);
    else if (ob < 6)
        gemm_body(g_xs, g_wks, blockIdx.x, ob - 3, 2, nullptr, 0, g_ksp);
    else
        gemm_body(g_xs, g_wvs, blockIdx.x, ob - 6, 0, g_v, DM, nullptr);
}

__global__ __launch_bounds__(128) void hmma_o(float* __restrict__ out)
{
    gemm_body(g_ys, g_wos, blockIdx.x, blockIdx.y, 0, out, DM, nullptr);
}

// ---------------- HMMA fused Based attention (128 rows, 8 warps) ----------
__global__ __launch_bounds__(256, 2) void attn_mma()
{
    __shared__ __align__(16) __nv_bfloat16 Qs[128][56];      // [n][48]
    __shared__ __align__(16) __nv_bfloat16 Ks[2][32][56];    // [m][48]
    __shared__ __align__(16) __nv_bfloat16 Vs[2][128][40];   // [e(hi|lo)][m32]

    const int t = threadIdx.x, warp = t >> 5, lane = t & 31;
    const int rb = blockIdx.x, bh = blockIdx.y;
    const int b = bh / Hh;
    const int gid = lane >> 2, tig = lane & 3;

    const __nv_bfloat16* Qb = g_qsp + ((size_t)bh * Ls + rb * 128) * 48;
    const __nv_bfloat16* Kb = g_ksp + (size_t)bh * Ls * 48;
    const __nv_bfloat16* Vb = g_vsp + (size_t)bh * 128 * Ls;

    const u32 sQ  = smem_u32(&Qs[0][0]);
    const u32 sK  = smem_u32(&Ks[0][0][0]);
    const u32 sV  = smem_u32(&Vs[0][0][0]);
    const u32 KBUF = 32 * 56 * 2, VBUF = 128 * 40 * 2;

    const int a_row = (lane & 7) + ((lane >> 3) & 1) * 8;
    const int a_col = ((lane >> 4) & 1) * 8;
    const int b_row = ((lane >> 4) & 1) * 8 + (lane & 7);
    const int b_col = ((lane >> 3) & 1) * 8;

    // Q tile: 128 rows x 6 vec16 = 768 vecs, 3/thread
    #pragma unroll
    for (int it = 0; it < 3; it++) {
        int idx = t + 256 * it;
        int r = idx / 6, j = idx % 6;
        cp_async16(sQ + (u32)(r * 112 + j * 16), Qb + (size_t)r * 48 + j * 8);
    }
    cp_commit();

    auto load_tile = [&](int mt, int buf) {
        const __nv_bfloat16* kp = Kb + (size_t)mt * 32 * 48;
        if (t < 192) {
            int r = t / 6, j = t % 6;
            cp_async16(sK + buf * KBUF + (u32)(r * 112 + j * 16),
                       kp + (size_t)r * 48 + j * 8);
        }
        #pragma unroll
        for (int it = 0; it < 2; it++) {
            int idx = t + 256 * it;
            int r = idx >> 2, j = idx & 3;
            cp_async16(sV + buf * VBUF + (u32)(r * 80 + j * 16),
                       Vb + (size_t)r * Ls + mt * 32 + j * 8);
        }
        cp_commit();
    };

    load_tile(0, 0);
    cp_wait<0>();
    __syncthreads();

    u32 aq[3][4];
    #pragma unroll
    for (int ks = 0; ks < 3; ks++)
        ldm_x4(aq[ks][0], aq[ks][1], aq[ks][2], aq[ks][3],
               sQ + (u32)((16 * warp + a_row) * 112 + (ks * 16 + a_col) * 2));

    float accy[8][4];
    #pragma unroll
    for (int eg = 0; eg < 8; eg++)
        #pragma unroll
        for (int j = 0; j < 4; j++) accy[eg][j] = 0.0f;
    float z0 = 0.0f, z1 = 0.0f;

    const int nA = rb * 128 + warp * 16 + gid;
    const int nB = nA + 8;

    #pragma unroll 1
    for (int mt = 0; mt < NMT; mt++) {
        const int cur = mt & 1;
        if (mt + 1 < NMT) { load_tile(mt + 1, 1 - cur); cp_wait<1>(); }
        else              { cp_wait<0>(); }
        __syncthreads();

        // ---- phase A: S[16n x 32m] per warp ----
        float sacc[4][4];
        #pragma unroll
        for (int cg = 0; cg < 4; cg++)
            #pragma unroll
            for (int j = 0; j < 4; j++) sacc[cg][j] = 0.0f;
        #pragma unroll
        for (int ks = 0; ks < 3; ks++) {
            u32 kb[2][4];
            #pragma unroll
            for (int g = 0; g < 2; g++)
                ldm_x4(kb[g][0], kb[g][1], kb[g][2], kb[g][3],
                       sK + cur * KBUF +
                       (u32)((g * 16 + b_row) * 112 + (ks * 16 + b_col) * 2));
            #pragma unroll
            for (int cg = 0; cg < 4; cg++)
                mma_bf16(sacc[cg][0], sacc[cg][1], sacc[cg][2], sacc[cg][3],
                         aq[ks][0], aq[ks][1], aq[ks][2], aq[ks][3],
                         kb[cg >> 1][(cg & 1) * 2], kb[cg >> 1][(cg & 1) * 2 + 1]);
        }

        // ---- transform s -> w in registers, pack into phase-B A-frags ----
        u32 ah[2][4], al[2][4];
        #pragma unroll
        for (int cg = 0; cg < 4; cg++) {
            int m0 = mt * 32 + cg * 8 + tig * 2;
            float w0 = fmaf(sacc[cg][0], fmaf(sacc[cg][0], 0.03125f, 0.25f), 1.0f);
            float w1 = fmaf(sacc[cg][1], fmaf(sacc[cg][1], 0.03125f, 0.25f), 1.0f);
            float w2 = fmaf(sacc[cg][2], fmaf(sacc[cg][2], 0.03125f, 0.25f), 1.0f);
            float w3 = fmaf(sacc[cg][3], fmaf(sacc[cg][3], 0.03125f, 0.25f), 1.0f);
            if (m0     <= nA) w0 += w0;
            if (m0 + 1 <= nA) w1 += w1;
            if (m0     <= nB) w2 += w2;
            if (m0 + 1 <= nB) w3 += w3;
            z0 += w0 + w1;
            z1 += w2 + w3;
            __nv_bfloat16 h0 = __float2bfloat16(w0), h1 = __float2bfloat16(w1);
            __nv_bfloat16 h2 = __float2bfloat16(w2), h3 = __float2bfloat16(w3);
            int c = cg >> 1, q = cg & 1;
            __nv_bfloat162 ph01 = {h0, h1}, ph23 = {h2, h3};
            ah[c][q * 2]     = *(u32*)&ph01;
            ah[c][q * 2 + 1] = *(u32*)&ph23;
            __nv_bfloat162 pl01 = {__float2bfloat16(w0 - __bfloat162float(h0)),
                                   __float2bfloat16(w1 - __bfloat162float(h1))};
            __nv_bfloat162 pl23 = {__float2bfloat16(w2 - __bfloat162float(h2)),
                                   __float2bfloat16(w3 - __bfloat162float(h3))};
            al[c][q * 2]     = *(u32*)&pl01;
            al[c][q * 2 + 1] = *(u32*)&pl23;
        }

        // ---- phase B: y += w*V (3-term), contraction 32m, V [e][m] -------
        #pragma unroll
        for (int c = 0; c < 2; c++) {
            u32 vh[4][4], vl[4][4];
            #pragma unroll
            for (int g = 0; g < 4; g++) {
                ldm_x4(vh[g][0], vh[g][1], vh[g][2], vh[g][3],
                       sV + cur * VBUF +
                       (u32)((g * 16 + b_row) * 80 + (c * 16 + b_col) * 2));
                ldm_x4(vl[g][0], vl[g][1], vl[g][2], vl[g][3],
                       sV + cur * VBUF + 64u * 80u +
                       (u32)((g * 16 + b_row) * 80 + (c * 16 + b_col) * 2));
            }
            #pragma unroll
            for (int eg = 0; eg < 8; eg++) {
                u32 bh0 = vh[eg >> 1][(eg & 1) * 2], bh1 = vh[eg >> 1][(eg & 1) * 2 + 1];
                u32 bl0 = vl[eg >> 1][(eg & 1) * 2], bl1 = vl[eg >> 1][(eg & 1) * 2 + 1];
                mma_bf16(accy[eg][0], accy[eg][1], accy[eg][2], accy[eg][3],
                         ah[c][0], ah[c][1], ah[c][2], ah[c][3], bh0, bh1);
                mma_bf16(accy[eg][0], accy[eg][1], accy[eg][2], accy[eg][3],
                         al[c][0], al[c][1], al[c][2], al[c][3], bh0, bh1);
                mma_bf16(accy[eg][0], accy[eg][1], accy[eg][2], accy[eg][3],
                         ah[c][0], ah[c][1], ah[c][2], ah[c][3], bl0, bl1);
            }
        }
        __syncthreads();
    }

    // ---- epilogue: reduce denominators, scale, write split ys directly ---
    z0 += __shfl_xor_sync(0xFFFFFFFF, z0, 1);
    z0 += __shfl_xor_sync(0xFFFFFFFF, z0, 2);
    z1 += __shfl_xor_sync(0xFFFFFFFF, z1, 1);
    z1 += __shfl_xor_sync(0xFFFFFFFF, z1, 2);
    float rz0 = 1.0f / z0, rz1 = 1.0f / z1;

    const int h = bh % Hh;
    __nv_bfloat16* yA = g_ys + (size_t)(b * Ls + nA) * K3 + h * HD;
    __nv_bfloat16* yB = g_ys + (size_t)(b * Ls + nB) * K3 + h * HD;
    #pragma unroll
    for (int eg = 0; eg < 8; eg++) {
        int e = eg * 8 + tig * 2;
        float y0 = accy[eg][0] * rz0, y1 = accy[eg][1] * rz0;
        float y2 = accy[eg][2] * rz1, y3 = accy[eg][3] * rz1;
        __nv_bfloat16 h0 = __float2bfloat16(y0), h1 = __float2bfloat16(y1);
        __nv_bfloat16 h2 = __float2bfloat16(y2), h3 = __float2bfloat16(y3);
        __nv_bfloat162 hA = {h0, h1}, hB = {h2, h3};
        __nv_bfloat162 lA = {__float2bfloat16(y0 - __bfloat162float(h0)),
                             __float2bfloat16(y1 - __bfloat162float(h1))};
        __nv_bfloat162 lB = {__float2bfloat16(y2 - __bfloat162float(h2)),
                             __float2bfloat16(y3 - __bfloat162float(h3))};
        *(__nv_bfloat162*)(yA + e)        = hA;
        *(__nv_bfloat162*)(yA + 768 + e)  = lA;
        *(__nv_bfloat162*)(yA + 1536 + e) = hA;
        *(__nv_bfloat162*)(yB + e)        = hB;
        *(__nv_bfloat162*)(yB + 768 + e)  = lB;
        *(__nv_bfloat162*)(yB + 1536 + e) = hB;
    }
}

// ---------------- launcher ------------------------------------------------
extern "C" void kernel_launch(void* const* d_in, const int* in_sizes, int n_in,
                              void* d_out, int out_size)
{
    const float* hs = (const float*)d_in[0];
    const float* Wq = (const float*)d_in[1];
    const float* Wk = (const float*)d_in[2];
    const float* Wv = (const float*)d_in[3];
    const float* Wo = (const float*)d_in[4];
    float* out = (float*)d_out;

    __nv_bfloat16 *pxs, *pwq, *pwk, *pwv, *pwo;
    cudaGetSymbolAddress((void**)&pxs, g_xs);
    cudaGetSymbolAddress((void**)&pwq, g_wqs);
    cudaGetSymbolAddress((void**)&pwk, g_wks);
    cudaGetSymbolAddress((void**)&pwv, g_wvs);
    cudaGetSymbolAddress((void**)&pwo, g_wos);

    // operand splits
    split_bf16<<<(NR*192 + 255)/256, 256>>>(hs, pxs, NR*192, 1);
    split_w2<<<(2*192*192 + 255)/256, 256>>>(Wq, Wk, pwq, pwk, 192*192);
    split_w2<<<(2*DM*192 + 255)/256, 256>>>(Wv, Wo, pwv, pwo, DM*192);

    // q,k,v projections in one launch; q/k write split head-major directly
    hmma_qkv<<<dim3(NR/128, 18), 128>>>();

    // v transpose+split for attention
    split_v_attn<<<(Bb*Hh*(Ls/8)*128 + 255)/256, 256>>>();

    // fused attention on tensor cores (writes split ys directly)
    attn_mma<<<dim3(Ls/128, Bb*Hh), 256>>>();

    // output projection
    hmma_o<<<dim3(NR/128, 12), 128>>>(out);
}